// round 1
// baseline (speedup 1.0000x reference)
#include <cuda_runtime.h>
#include <cuda_bf16.h>
#include <math.h>

#define BDIM  8
#define C2D   256
#define NTOK  1024
#define NHEAD 8
#define DHEAD 32
#define KCL   3
#define QKSCALE 0.17677669529663687f

// ---------------- scratch (device globals; no allocation allowed) ----------
__device__ float g_xf  [BDIM * C2D * NTOK];        // proj_in output  [b][c][n]
__device__ float g_qkv [BDIM * 3 * C2D * NTOK];    // qkv             [b][o][n]
__device__ float g_prob[BDIM * KCL * NTOK];        // cluster probs   [b][k][n]
__device__ float g_att [BDIM * C2D * NTOK];        // attention out   [b][c][n]

// ---------------- generic batched GEMM: C[b] = A @ X[b] (+ addend[b]) ------
// A: [M,K] row-major shared across batch; X: [B][K,NTOK]; C: [B][M,NTOK]
__global__ __launch_bounds__(256) void gemm_bn(
    const float* __restrict__ A, const float* __restrict__ X,
    float* __restrict__ C, const float* __restrict__ add_src,
    int M, int K)
{
    __shared__ float Asm[16][68];
    __shared__ float Bsm[16][68];

    const int b = blockIdx.z;
    const float* Xb = X + (size_t)b * K * NTOK;
    float* Cb = C + (size_t)b * M * NTOK;

    const int t  = threadIdx.x;
    const int tx = t & 15, ty = t >> 4;
    const int mblk = blockIdx.y * 64, nblk = blockIdx.x * 64;
    const int m0 = ty * 4, n0 = tx * 4;
    const int a_mm = t >> 2,  a_k4 = (t & 3) << 2;
    const int b_kk = t >> 4,  b_nn = (t & 15) << 2;

    float acc[4][4];
#pragma unroll
    for (int i = 0; i < 4; i++)
#pragma unroll
        for (int j = 0; j < 4; j++) acc[i][j] = 0.f;

    for (int kt = 0; kt < K; kt += 16) {
        __syncthreads();
        float4 av = *(const float4*)(A + (size_t)(mblk + a_mm) * K + kt + a_k4);
        Asm[a_k4 + 0][a_mm] = av.x;
        Asm[a_k4 + 1][a_mm] = av.y;
        Asm[a_k4 + 2][a_mm] = av.z;
        Asm[a_k4 + 3][a_mm] = av.w;
        *(float4*)(&Bsm[b_kk][b_nn]) =
            *(const float4*)(Xb + (size_t)(kt + b_kk) * NTOK + nblk + b_nn);
        __syncthreads();
#pragma unroll
        for (int kk = 0; kk < 16; kk++) {
            float4 a4 = *(const float4*)(&Asm[kk][m0]);
            float4 b4 = *(const float4*)(&Bsm[kk][n0]);
            float a[4]  = {a4.x, a4.y, a4.z, a4.w};
            float bb[4] = {b4.x, b4.y, b4.z, b4.w};
#pragma unroll
            for (int i = 0; i < 4; i++)
#pragma unroll
                for (int j = 0; j < 4; j++)
                    acc[i][j] = fmaf(a[i], bb[j], acc[i][j]);
        }
    }

#pragma unroll
    for (int i = 0; i < 4; i++) {
        size_t off = (size_t)(mblk + m0 + i) * NTOK + nblk + n0;
        float4 o = make_float4(acc[i][0], acc[i][1], acc[i][2], acc[i][3]);
        if (add_src) {
            float4 ad = *(const float4*)(add_src + (size_t)b * M * NTOK + off);
            o.x += ad.x; o.y += ad.y; o.z += ad.z; o.w += ad.w;
        }
        *(float4*)(Cb + off) = o;
    }
}

// ---------------- cluster logits + softmax over KCL=3 ----------------------
__global__ __launch_bounds__(256) void prob_kernel(
    const float* __restrict__ Wc, const float* __restrict__ bc)
{
    __shared__ float W[KCL * C2D];
    __shared__ float bias[KCL];
    const int t = threadIdx.x;
    for (int i = t; i < KCL * C2D; i += 256) W[i] = Wc[i];
    if (t < KCL) bias[t] = bc[t];
    __syncthreads();

    const int g = blockIdx.x * 256 + t;
    const int b = g >> 10, n = g & 1023;
    float l0 = bias[0], l1 = bias[1], l2 = bias[2];
    const float* xb = g_xf + (size_t)b * C2D * NTOK + n;
#pragma unroll 4
    for (int c = 0; c < C2D; c++) {
        float xv = xb[(size_t)c * NTOK];
        l0 = fmaf(W[c],           xv, l0);
        l1 = fmaf(W[C2D + c],     xv, l1);
        l2 = fmaf(W[2 * C2D + c], xv, l2);
    }
    float mx = fmaxf(l0, fmaxf(l1, l2));
    float e0 = __expf(l0 - mx), e1 = __expf(l1 - mx), e2 = __expf(l2 - mx);
    float inv = 1.f / (e0 + e1 + e2);
    float* pb = g_prob + (size_t)b * KCL * NTOK + n;
    pb[0]        = e0 * inv;
    pb[NTOK]     = e1 * inv;
    pb[2 * NTOK] = e2 * inv;
}

// ---------------- attention ------------------------------------------------
// Block = (row_tile 128, head, batch). Gram matrix G = Q·K^T shared across the
// 3 clusters (S_i = pn_i * pm_i * G * scale), flash-style online softmax.
// Dynamic smem layout (floats):
//   S  [128][129]  @ 0       (16512)
//   Qs [32][132]   @ 16512   (4224)   Q stored [d][r]
//   Ks [32][132]   @ 20736   (4224)   K stored [d][m]
//   Vs [128][36]   @ 24960   (4608)   V stored [m][d] (pitch 36 -> f4 aligned)
//   Pm [3][128]    @ 29568   (384)
#define ATT_SMEM_FLOATS 29952
#define ATT_SMEM_BYTES  (ATT_SMEM_FLOATS * 4)

__global__ __launch_bounds__(256) void attn_kernel()
{
    extern __shared__ float sm[];
    float* S  = sm;
    float* Qs = sm + 16512;
    float* Ks = sm + 20736;
    float* Vs = sm + 24960;
    float* Pm = sm + 29568;

    const int t  = threadIdx.x;
    const int n0 = blockIdx.x * 128;
    const int h  = blockIdx.y;
    const int b  = blockIdx.z;

    const float* qbase = g_qkv + ((size_t)b * 3 * C2D + h * DHEAD) * NTOK;
    const float* kbase = qbase + (size_t)C2D * NTOK;
    const float* vbase = qbase + (size_t)2 * C2D * NTOK;
    const float* pbase = g_prob + (size_t)b * KCL * NTOK;

    // load Q tile once: Qs[d][r]
    for (int idx = t; idx < DHEAD * 128; idx += 256) {
        int d = idx >> 7, r = idx & 127;
        Qs[d * 132 + r] = qbase[(size_t)d * NTOK + n0 + r];
    }

    const int r  = t >> 1;          // row owned in softmax/PV phase
    const int dh = (t & 1) * 16;    // d-half owned
    float pnr[KCL];
#pragma unroll
    for (int i = 0; i < KCL; i++) pnr[i] = pbase[i * NTOK + n0 + r];

    float mrun[KCL], lrun[KCL], oacc[KCL][16];
#pragma unroll
    for (int i = 0; i < KCL; i++) {
        mrun[i] = -INFINITY; lrun[i] = 0.f;
#pragma unroll
        for (int j = 0; j < 16; j++) oacc[i][j] = 0.f;
    }

    const int ty = t >> 4, tx = t & 15;
    const int r0 = ty * 8, c0 = tx * 8;   // G-phase micro-tile origin

    for (int mt = 0; mt < NTOK; mt += 128) {
        __syncthreads();
        // load K[d][m], V[m][d], Pm[i][m]
        for (int idx = t; idx < DHEAD * 128; idx += 256) {
            int d = idx >> 7, m = idx & 127;
            float kv = kbase[(size_t)d * NTOK + mt + m];
            float vv = vbase[(size_t)d * NTOK + mt + m];
            Ks[d * 132 + m] = kv;
            Vs[m * 36 + d]  = vv;
        }
        if (t < KCL * 128) {
            int i = t >> 7, m = t & 127;
            Pm[i * 128 + m] = pbase[i * NTOK + mt + m];
        }
        __syncthreads();

        // ---- G = Q^T K tile: 16x16 threads, 8x8 micro ----
        float g[8][8];
#pragma unroll
        for (int ii = 0; ii < 8; ii++)
#pragma unroll
            for (int jj = 0; jj < 8; jj++) g[ii][jj] = 0.f;
#pragma unroll 4
        for (int d = 0; d < DHEAD; d++) {
            float4 a0 = *(const float4*)(Qs + d * 132 + r0);
            float4 a1 = *(const float4*)(Qs + d * 132 + r0 + 4);
            float4 b0 = *(const float4*)(Ks + d * 132 + c0);
            float4 b1 = *(const float4*)(Ks + d * 132 + c0 + 4);
            float av[8] = {a0.x, a0.y, a0.z, a0.w, a1.x, a1.y, a1.z, a1.w};
            float bv[8] = {b0.x, b0.y, b0.z, b0.w, b1.x, b1.y, b1.z, b1.w};
#pragma unroll
            for (int ii = 0; ii < 8; ii++)
#pragma unroll
                for (int jj = 0; jj < 8; jj++)
                    g[ii][jj] = fmaf(av[ii], bv[jj], g[ii][jj]);
        }
#pragma unroll
        for (int ii = 0; ii < 8; ii++)
#pragma unroll
            for (int jj = 0; jj < 8; jj++)
                S[(r0 + ii) * 129 + c0 + jj] = g[ii][jj];
        __syncthreads();

        // ---- per-cluster online softmax + PV ----
        const float* Srow = S + r * 129;
#pragma unroll
        for (int i = 0; i < KCL; i++) {
            const float cr = QKSCALE * pnr[i];
            const float* pmv = Pm + i * 128;

            // pass 1: tile max over this thread's m-half, combine with partner
            float mymax = -INFINITY;
            const int mb = (t & 1) * 64;
#pragma unroll 4
            for (int m = mb; m < mb + 64; m++) {
                float v = cr * Srow[m] * pmv[m];
                mymax = fmaxf(mymax, v);
            }
            mymax = fmaxf(mymax, __shfl_xor_sync(0xffffffffu, mymax, 1));
            float nm = fmaxf(mrun[i], mymax);
            float f  = __expf(mrun[i] - nm);
            mrun[i] = nm;
            lrun[i] *= f;
#pragma unroll
            for (int j = 0; j < 16; j++) oacc[i][j] *= f;

            // pass 2: exp + PV over full 128 m (both row-threads full range)
            float lsum = 0.f;
#pragma unroll 2
            for (int m = 0; m < 128; m++) {
                float pm = pmv[m];
                float e  = __expf(cr * Srow[m] * pm - nm);
                lsum += e;
                float w = e * pm;   // masked V: v_i = pm * v
                const float* vp = Vs + m * 36 + dh;
                float4 v0 = *(const float4*)(vp);
                float4 v1 = *(const float4*)(vp + 4);
                float4 v2 = *(const float4*)(vp + 8);
                float4 v3 = *(const float4*)(vp + 12);
                oacc[i][0]  = fmaf(w, v0.x, oacc[i][0]);
                oacc[i][1]  = fmaf(w, v0.y, oacc[i][1]);
                oacc[i][2]  = fmaf(w, v0.z, oacc[i][2]);
                oacc[i][3]  = fmaf(w, v0.w, oacc[i][3]);
                oacc[i][4]  = fmaf(w, v1.x, oacc[i][4]);
                oacc[i][5]  = fmaf(w, v1.y, oacc[i][5]);
                oacc[i][6]  = fmaf(w, v1.z, oacc[i][6]);
                oacc[i][7]  = fmaf(w, v1.w, oacc[i][7]);
                oacc[i][8]  = fmaf(w, v2.x, oacc[i][8]);
                oacc[i][9]  = fmaf(w, v2.y, oacc[i][9]);
                oacc[i][10] = fmaf(w, v2.z, oacc[i][10]);
                oacc[i][11] = fmaf(w, v2.w, oacc[i][11]);
                oacc[i][12] = fmaf(w, v3.x, oacc[i][12]);
                oacc[i][13] = fmaf(w, v3.y, oacc[i][13]);
                oacc[i][14] = fmaf(w, v3.z, oacc[i][14]);
                oacc[i][15] = fmaf(w, v3.w, oacc[i][15]);
            }
            lrun[i] += lsum;
        }
    }

    // epilogue: out[n,d] = (1/3) * sum_i oacc_i / l_i ; layout [b][h*32+d][n]
    float* obase = g_att + ((size_t)b * C2D + h * DHEAD + dh) * NTOK + n0 + r;
    const float inv0 = 1.f / (3.f * lrun[0]);
    const float inv1 = 1.f / (3.f * lrun[1]);
    const float inv2 = 1.f / (3.f * lrun[2]);
#pragma unroll
    for (int j = 0; j < 16; j++) {
        float o = oacc[0][j] * inv0 + oacc[1][j] * inv1 + oacc[2][j] * inv2;
        obase[(size_t)j * NTOK] = o;
    }
}

// ---------------- launch ----------------------------------------------------
extern "C" void kernel_launch(void* const* d_in, const int* in_sizes, int n_in,
                              void* d_out, int out_size)
{
    const float* x      = (const float*)d_in[0];
    const float* W_in   = (const float*)d_in[1];
    const float* Wc     = (const float*)d_in[2];
    const float* bc     = (const float*)d_in[3];
    const float* W_qkv  = (const float*)d_in[4];
    const float* W_proj = (const float*)d_in[5];
    float* out = (float*)d_out;

    float *xf, *qkv, *att;
    cudaGetSymbolAddress((void**)&xf,  g_xf);
    cudaGetSymbolAddress((void**)&qkv, g_qkv);
    cudaGetSymbolAddress((void**)&att, g_att);

    cudaFuncSetAttribute(attn_kernel,
                         cudaFuncAttributeMaxDynamicSharedMemorySize,
                         ATT_SMEM_BYTES);

    // 1) xf = W_in @ x          (M=256, K=128)
    gemm_bn<<<dim3(16, 4, BDIM), 256>>>(W_in, x, xf, nullptr, 256, 128);
    // 2) cluster probs
    prob_kernel<<<(BDIM * NTOK) / 256, 256>>>(Wc, bc);
    // 3) qkv = W_qkv @ xf       (M=768, K=256)
    gemm_bn<<<dim3(16, 12, BDIM), 256>>>(W_qkv, xf, qkv, nullptr, 768, 256);
    // 4) clustered attention
    attn_kernel<<<dim3(NTOK / 128, NHEAD, BDIM), 256, ATT_SMEM_BYTES>>>();
    // 5) out = W_proj @ att + xf
    gemm_bn<<<dim3(16, 4, BDIM), 256>>>(W_proj, att, out, xf, 256, 256);
}

// round 4
// speedup vs baseline: 2.7873x; 2.7873x over previous
#include <cuda_runtime.h>
#include <cuda_bf16.h>
#include <math.h>
#include <stdint.h>

#define BDIM  8
#define C2D   256
#define NTOK  1024
#define NHEAD 8
#define DHEAD 32
#define KCL   3
#define QKSCALE 0.17677669529663687f

// ---------------- scratch ----------------
__device__ float g_xf  [BDIM * C2D * NTOK];
__device__ float g_qkv [BDIM * 3 * C2D * NTOK];
__device__ float g_prob[BDIM * KCL * NTOK];
__device__ float g_att [BDIM * C2D * NTOK];

// ---------------- mma.sync helpers (base-target PTX, legacy HMMA) ----------
__device__ __forceinline__ void mma16816(float* d,
    uint32_t a0, uint32_t a1, uint32_t a2, uint32_t a3,
    uint32_t b0, uint32_t b1)
{
    asm volatile(
        "mma.sync.aligned.m16n8k16.row.col.f32.bf16.bf16.f32 "
        "{%0,%1,%2,%3}, {%4,%5,%6,%7}, {%8,%9}, {%0,%1,%2,%3};"
        : "+f"(d[0]), "+f"(d[1]), "+f"(d[2]), "+f"(d[3])
        : "r"(a0), "r"(a1), "r"(a2), "r"(a3), "r"(b0), "r"(b1));
}

__device__ __forceinline__ uint32_t packbf(float lo, float hi) {
    __nv_bfloat162 p = __floats2bfloat162_rn(lo, hi);
    return *(uint32_t*)&p;
}

// ---------------- attention ------------------------------------------------
// CTA = (64-row tile, head, batch); 4 warps x 16 rows.
// S = Q K^T via m16n8k16; exp applied in accumulator registers; P re-packed
// into A fragments for O += P V^T. No S/P smem round-trip.
#define ROWT 64
#define KS_LD 40      // Ks[m][d] bf16, stride 40 halfwords
#define VT_LD 136     // Vt[d][m] bf16, stride 136 halfwords

__global__ void __launch_bounds__(128) attn_kernel()
{
    __shared__ __align__(16) __nv_bfloat16 Ks[128 * KS_LD];
    __shared__ __align__(16) __nv_bfloat16 Vt[DHEAD * VT_LD];
    __shared__ float pm_s[KCL * 128];

    const int t    = threadIdx.x;
    const int wid  = t >> 5;
    const int lane = t & 31;
    const int gid  = lane >> 2;          // 0..7
    const int q2   = (lane & 3) * 2;     // 0,2,4,6

    const int n0 = blockIdx.x * ROWT;
    const int h  = blockIdx.y;
    const int b  = blockIdx.z;

    const float* qbase = g_qkv + ((size_t)b * 3 * C2D + h * DHEAD) * NTOK;
    const float* kbase = qbase + (size_t)C2D * NTOK;
    const float* vbase = qbase + (size_t)2 * C2D * NTOK;
    const float* pbase = g_prob + (size_t)b * KCL * NTOK;

    const int n_g = n0 + wid * 16 + gid;   // row r0 (global); r1 = n_g + 8

    // ---- Q fragments (2 k-halves x 4 b32), straight from global ----
    uint32_t qa[2][4];
#pragma unroll
    for (int kt = 0; kt < 2; kt++) {
        int d0 = kt * 16 + q2;
        qa[kt][0] = packbf(qbase[(size_t)d0 * NTOK + n_g],
                           qbase[(size_t)(d0 + 1) * NTOK + n_g]);
        qa[kt][1] = packbf(qbase[(size_t)d0 * NTOK + n_g + 8],
                           qbase[(size_t)(d0 + 1) * NTOK + n_g + 8]);
        qa[kt][2] = packbf(qbase[(size_t)(d0 + 8) * NTOK + n_g],
                           qbase[(size_t)(d0 + 9) * NTOK + n_g]);
        qa[kt][3] = packbf(qbase[(size_t)(d0 + 8) * NTOK + n_g + 8],
                           qbase[(size_t)(d0 + 9) * NTOK + n_g + 8]);
    }

    float pn0[KCL], pn1[KCL];
#pragma unroll
    for (int i = 0; i < KCL; i++) {
        pn0[i] = pbase[i * NTOK + n_g];
        pn1[i] = pbase[i * NTOK + n_g + 8];
    }

    float oacc[KCL][4][4];   // [cluster][d-tile][frag]
    float lacc[KCL][2];
#pragma unroll
    for (int i = 0; i < KCL; i++) {
        lacc[i][0] = lacc[i][1] = 0.f;
#pragma unroll
        for (int dt = 0; dt < 4; dt++)
#pragma unroll
            for (int j = 0; j < 4; j++) oacc[i][dt][j] = 0.f;
    }

    for (int mt = 0; mt < NTOK; mt += 128) {
        __syncthreads();   // prior iteration's MMAs done before restaging
        // ---- stage K[m][d], V^T[d][m], pm ----
        for (int idx = t; idx < DHEAD * 128; idx += 128) {
            int d = idx >> 7, m = idx & 127;
            Ks[m * KS_LD + d] = __float2bfloat16(kbase[(size_t)d * NTOK + mt + m]);
            Vt[d * VT_LD + m] = __float2bfloat16(vbase[(size_t)d * NTOK + mt + m]);
        }
        for (int idx = t; idx < KCL * 128; idx += 128) {
            int i = idx >> 7, m = idx & 127;
            pm_s[i * 128 + m] = pbase[(size_t)i * NTOK + mt + m];
        }
        __syncthreads();

        // ---- S = Q K^T : 16 col-tiles of 8 ----
        float sacc[16][4];
#pragma unroll
        for (int nt = 0; nt < 16; nt++) {
            sacc[nt][0] = sacc[nt][1] = sacc[nt][2] = sacc[nt][3] = 0.f;
            const __nv_bfloat16* kp = Ks + (nt * 8 + gid) * KS_LD;
            uint32_t b0 = *(const uint32_t*)(kp + q2);
            uint32_t b1 = *(const uint32_t*)(kp + q2 + 8);
            mma16816(sacc[nt], qa[0][0], qa[0][1], qa[0][2], qa[0][3], b0, b1);
            b0 = *(const uint32_t*)(kp + 16 + q2);
            b1 = *(const uint32_t*)(kp + 16 + q2 + 8);
            mma16816(sacc[nt], qa[1][0], qa[1][1], qa[1][2], qa[1][3], b0, b1);
        }

        // ---- per-cluster: exp in-register, feed PV mma directly ----
#pragma unroll
        for (int i = 0; i < KCL; i++) {
            const float cr0 = QKSCALE * pn0[i];
            const float cr1 = QKSCALE * pn1[i];
            const float* pmp = pm_s + i * 128;
            float l0 = 0.f, l1 = 0.f;
#pragma unroll
            for (int s = 0; s < 8; s++) {
                const float* pc = pmp + 16 * s;
                float pm00 = pc[q2],     pm01 = pc[q2 + 1];
                float pm10 = pc[q2 + 8], pm11 = pc[q2 + 9];
                const int j0 = 2 * s, j1 = 2 * s + 1;
                float e00 = __expf(sacc[j0][0] * cr0 * pm00);
                float e01 = __expf(sacc[j0][1] * cr0 * pm01);
                float e02 = __expf(sacc[j0][2] * cr1 * pm00);
                float e03 = __expf(sacc[j0][3] * cr1 * pm01);
                float e10 = __expf(sacc[j1][0] * cr0 * pm10);
                float e11 = __expf(sacc[j1][1] * cr0 * pm11);
                float e12 = __expf(sacc[j1][2] * cr1 * pm10);
                float e13 = __expf(sacc[j1][3] * cr1 * pm11);
                l0 += e00 + e01 + e10 + e11;
                l1 += e02 + e03 + e12 + e13;
                uint32_t ra0 = packbf(e00 * pm00, e01 * pm01);
                uint32_t ra1 = packbf(e02 * pm00, e03 * pm01);
                uint32_t ra2 = packbf(e10 * pm10, e11 * pm11);
                uint32_t ra3 = packbf(e12 * pm10, e13 * pm11);
#pragma unroll
                for (int dt = 0; dt < 4; dt++) {
                    const __nv_bfloat16* vp = Vt + (dt * 8 + gid) * VT_LD + 16 * s;
                    uint32_t vb0 = *(const uint32_t*)(vp + q2);
                    uint32_t vb1 = *(const uint32_t*)(vp + q2 + 8);
                    mma16816(oacc[i][dt], ra0, ra1, ra2, ra3, vb0, vb1);
                }
            }
            lacc[i][0] += l0;
            lacc[i][1] += l1;
        }
    }

    // ---- reduce l across the 4 lanes sharing a row, finalize, store ----
    float inv0[KCL], inv1[KCL];
#pragma unroll
    for (int i = 0; i < KCL; i++) {
        float l0 = lacc[i][0], l1 = lacc[i][1];
        l0 += __shfl_xor_sync(0xffffffffu, l0, 1);
        l0 += __shfl_xor_sync(0xffffffffu, l0, 2);
        l1 += __shfl_xor_sync(0xffffffffu, l1, 1);
        l1 += __shfl_xor_sync(0xffffffffu, l1, 2);
        inv0[i] = __fdividef(1.f, 3.f * l0);
        inv1[i] = __fdividef(1.f, 3.f * l1);
    }

    float* ob = g_att + ((size_t)b * C2D + h * DHEAD) * NTOK;
#pragma unroll
    for (int dt = 0; dt < 4; dt++) {
        int d0 = dt * 8 + q2;
        float o00 = 0.f, o01 = 0.f, o10 = 0.f, o11 = 0.f;
#pragma unroll
        for (int i = 0; i < KCL; i++) {
            o00 += oacc[i][dt][0] * inv0[i];
            o01 += oacc[i][dt][1] * inv0[i];
            o10 += oacc[i][dt][2] * inv1[i];
            o11 += oacc[i][dt][3] * inv1[i];
        }
        ob[(size_t)d0 * NTOK + n_g]           = o00;
        ob[(size_t)(d0 + 1) * NTOK + n_g]     = o01;
        ob[(size_t)d0 * NTOK + n_g + 8]       = o10;
        ob[(size_t)(d0 + 1) * NTOK + n_g + 8] = o11;
    }
}

// ---------------- generic batched GEMM (unchanged) ----------------
__global__ __launch_bounds__(256) void gemm_bn(
    const float* __restrict__ A, const float* __restrict__ X,
    float* __restrict__ C, const float* __restrict__ add_src,
    int M, int K)
{
    __shared__ float Asm[16][68];
    __shared__ float Bsm[16][68];

    const int b = blockIdx.z;
    const float* Xb = X + (size_t)b * K * NTOK;
    float* Cb = C + (size_t)b * M * NTOK;

    const int t  = threadIdx.x;
    const int tx = t & 15, ty = t >> 4;
    const int mblk = blockIdx.y * 64, nblk = blockIdx.x * 64;
    const int m0 = ty * 4, n0 = tx * 4;
    const int a_mm = t >> 2,  a_k4 = (t & 3) << 2;
    const int b_kk = t >> 4,  b_nn = (t & 15) << 2;

    float acc[4][4];
#pragma unroll
    for (int i = 0; i < 4; i++)
#pragma unroll
        for (int j = 0; j < 4; j++) acc[i][j] = 0.f;

    for (int kt = 0; kt < K; kt += 16) {
        __syncthreads();
        float4 av = *(const float4*)(A + (size_t)(mblk + a_mm) * K + kt + a_k4);
        Asm[a_k4 + 0][a_mm] = av.x;
        Asm[a_k4 + 1][a_mm] = av.y;
        Asm[a_k4 + 2][a_mm] = av.z;
        Asm[a_k4 + 3][a_mm] = av.w;
        *(float4*)(&Bsm[b_kk][b_nn]) =
            *(const float4*)(Xb + (size_t)(kt + b_kk) * NTOK + nblk + b_nn);
        __syncthreads();
#pragma unroll
        for (int kk = 0; kk < 16; kk++) {
            float4 a4 = *(const float4*)(&Asm[kk][m0]);
            float4 b4 = *(const float4*)(&Bsm[kk][n0]);
            float a[4]  = {a4.x, a4.y, a4.z, a4.w};
            float bb[4] = {b4.x, b4.y, b4.z, b4.w};
#pragma unroll
            for (int i = 0; i < 4; i++)
#pragma unroll
                for (int j = 0; j < 4; j++)
                    acc[i][j] = fmaf(a[i], bb[j], acc[i][j]);
        }
    }

#pragma unroll
    for (int i = 0; i < 4; i++) {
        size_t off = (size_t)(mblk + m0 + i) * NTOK + nblk + n0;
        float4 o = make_float4(acc[i][0], acc[i][1], acc[i][2], acc[i][3]);
        if (add_src) {
            float4 ad = *(const float4*)(add_src + (size_t)b * M * NTOK + off);
            o.x += ad.x; o.y += ad.y; o.z += ad.z; o.w += ad.w;
        }
        *(float4*)(Cb + off) = o;
    }
}

// ---------------- cluster probs (unchanged) ----------------
__global__ __launch_bounds__(256) void prob_kernel(
    const float* __restrict__ Wc, const float* __restrict__ bc)
{
    __shared__ float W[KCL * C2D];
    __shared__ float bias[KCL];
    const int t = threadIdx.x;
    for (int i = t; i < KCL * C2D; i += 256) W[i] = Wc[i];
    if (t < KCL) bias[t] = bc[t];
    __syncthreads();

    const int gidx = blockIdx.x * 256 + t;
    const int b = gidx >> 10, n = gidx & 1023;
    float l0 = bias[0], l1 = bias[1], l2 = bias[2];
    const float* xb = g_xf + (size_t)b * C2D * NTOK + n;
#pragma unroll 4
    for (int c = 0; c < C2D; c++) {
        float xv = xb[(size_t)c * NTOK];
        l0 = fmaf(W[c],           xv, l0);
        l1 = fmaf(W[C2D + c],     xv, l1);
        l2 = fmaf(W[2 * C2D + c], xv, l2);
    }
    float mx = fmaxf(l0, fmaxf(l1, l2));
    float e0 = __expf(l0 - mx), e1 = __expf(l1 - mx), e2 = __expf(l2 - mx);
    float inv = 1.f / (e0 + e1 + e2);
    float* pb = g_prob + (size_t)b * KCL * NTOK + n;
    pb[0]        = e0 * inv;
    pb[NTOK]     = e1 * inv;
    pb[2 * NTOK] = e2 * inv;
}

// ---------------- launch ----------------
extern "C" void kernel_launch(void* const* d_in, const int* in_sizes, int n_in,
                              void* d_out, int out_size)
{
    const float* x      = (const float*)d_in[0];
    const float* W_in   = (const float*)d_in[1];
    const float* Wc     = (const float*)d_in[2];
    const float* bc     = (const float*)d_in[3];
    const float* W_qkv  = (const float*)d_in[4];
    const float* W_proj = (const float*)d_in[5];
    float* out = (float*)d_out;

    float *xf, *qkv, *att;
    cudaGetSymbolAddress((void**)&xf,  g_xf);
    cudaGetSymbolAddress((void**)&qkv, g_qkv);
    cudaGetSymbolAddress((void**)&att, g_att);

    // 1) xf = W_in @ x          (M=256, K=128)
    gemm_bn<<<dim3(16, 4, BDIM), 256>>>(W_in, x, xf, nullptr, 256, 128);
    // 2) cluster probs
    prob_kernel<<<(BDIM * NTOK) / 256, 256>>>(Wc, bc);
    // 3) qkv = W_qkv @ xf       (M=768, K=256)
    gemm_bn<<<dim3(16, 12, BDIM), 256>>>(W_qkv, xf, qkv, nullptr, 768, 256);
    // 4) clustered attention (mma.sync bf16, register-resident S/P)
    attn_kernel<<<dim3(NTOK / ROWT, NHEAD, BDIM), 128>>>();
    // 5) out = W_proj @ att + xf
    gemm_bn<<<dim3(16, 4, BDIM), 256>>>(W_proj, att, out, xf, 256, 256);
}

// round 6
// speedup vs baseline: 3.4964x; 1.2544x over previous
#include <cuda_runtime.h>
#include <cuda_bf16.h>
#include <math.h>
#include <stdint.h>

#define BDIM  8
#define C2D   256
#define NTOK  1024
#define NHEAD 8
#define DHEAD 32
#define KCL   3
#define QKSCALE 0.17677669529663687f
#define EXPSC  (0.17677669529663687f * 1.4426950408889634f)

// ---------------- scratch ----------------
__device__ float g_xf  [BDIM * C2D * NTOK];            // fp32 proj_in (identity)
__device__ float g_qkv [BDIM * 3 * C2D * NTOK];        // fp32 qkv
__device__ float g_prob[BDIM * KCL * NTOK];            // raw probs
__device__ float g_probe[BDIM * KCL * NTOK];           // probs * SCALE*log2e
__device__ __nv_bfloat16 g_wqh [3 * C2D * C2D];        // W_qkv bf16
__device__ __nv_bfloat16 g_wph [C2D * C2D];            // W_proj bf16
__device__ __nv_bfloat16 g_xft [BDIM * NTOK * C2D];    // xf^T bf16 [b][n][k]
__device__ __nv_bfloat16 g_qh  [BDIM * NHEAD * NTOK * DHEAD]; // [b][h][n][d]
__device__ __nv_bfloat16 g_kh  [BDIM * NHEAD * NTOK * DHEAD]; // [b][h][m][d]
__device__ __nv_bfloat16 g_vh  [BDIM * NHEAD * DHEAD * NTOK]; // [b][h][d][m]
__device__ __nv_bfloat16 g_attt[BDIM * NTOK * C2D];    // attn out^T bf16 [b][n][c]

// ---------------- helpers ----------------
__device__ __forceinline__ void mma16816(float* d,
    uint32_t a0, uint32_t a1, uint32_t a2, uint32_t a3,
    uint32_t b0, uint32_t b1)
{
    asm volatile(
        "mma.sync.aligned.m16n8k16.row.col.f32.bf16.bf16.f32 "
        "{%0,%1,%2,%3}, {%4,%5,%6,%7}, {%8,%9}, {%0,%1,%2,%3};"
        : "+f"(d[0]), "+f"(d[1]), "+f"(d[2]), "+f"(d[3])
        : "r"(a0), "r"(a1), "r"(a2), "r"(a3), "r"(b0), "r"(b1));
}
__device__ __forceinline__ uint32_t packbf(float lo, float hi) {
    __nv_bfloat162 p = __floats2bfloat162_rn(lo, hi);
    return *(uint32_t*)&p;
}
__device__ __forceinline__ float ex2f(float x) {
    float r; asm("ex2.approx.ftz.f32 %0, %1;" : "=f"(r) : "f"(x)); return r;
}

// ---------------- bf16 GEMM: C[b] = A @ Xt[b]^T (+add) ---------------------
// A bf16 [M,256] row-major; Xt bf16 [b][1024][256] (row n holds k 0..255);
// C fp32 [b][M][1024]. CTA = 64m x 64n, 128 threads, whole K=256 in smem.
#define GK 256
#define GLD 264
#define GEMMH_SMEM (2 * 64 * GLD * 2)
__global__ __launch_bounds__(128) void gemm_h(
    const __nv_bfloat16* __restrict__ Ah, const __nv_bfloat16* __restrict__ Xt,
    float* __restrict__ C, const float* __restrict__ add_src, int M)
{
    extern __shared__ __nv_bfloat16 gs[];
    __nv_bfloat16* As = gs;
    __nv_bfloat16* Bs = gs + 64 * GLD;

    const int t = threadIdx.x;
    const int lane = t & 31, wid = t >> 5;
    const int gid = lane >> 2, q2 = (lane & 3) * 2;
    const int mblk = blockIdx.y * 64, nblk = blockIdx.x * 64, b = blockIdx.z;

    const __nv_bfloat16* Xb = Xt + ((size_t)b * NTOK + nblk) * GK;
#pragma unroll
    for (int i = 0; i < 16; i++) {
        int idx = t + i * 128;
        int row = idx >> 5, q = (idx & 31) * 8;
        *(uint4*)(As + row * GLD + q) = *(const uint4*)(Ah + (size_t)(mblk + row) * GK + q);
        *(uint4*)(Bs + row * GLD + q) = *(const uint4*)(Xb + (size_t)row * GK + q);
    }
    __syncthreads();

    const int wm = wid * 16;
    float acc[8][4];
#pragma unroll
    for (int nt = 0; nt < 8; nt++)
#pragma unroll
        for (int j = 0; j < 4; j++) acc[nt][j] = 0.f;

#pragma unroll
    for (int kt = 0; kt < GK / 16; kt++) {
        const int ka = kt * 16 + q2;
        uint32_t a0 = *(const uint32_t*)(As + (wm + gid) * GLD + ka);
        uint32_t a1 = *(const uint32_t*)(As + (wm + gid + 8) * GLD + ka);
        uint32_t a2 = *(const uint32_t*)(As + (wm + gid) * GLD + ka + 8);
        uint32_t a3 = *(const uint32_t*)(As + (wm + gid + 8) * GLD + ka + 8);
#pragma unroll
        for (int nt = 0; nt < 8; nt++) {
            uint32_t b0 = *(const uint32_t*)(Bs + (nt * 8 + gid) * GLD + ka);
            uint32_t b1 = *(const uint32_t*)(Bs + (nt * 8 + gid) * GLD + ka + 8);
            mma16816(acc[nt], a0, a1, a2, a3, b0, b1);
        }
    }

    float* Cb = C + (size_t)b * M * NTOK;
    const int r0 = mblk + wm + gid;
#pragma unroll
    for (int nt = 0; nt < 8; nt++) {
        int col = nblk + nt * 8 + q2;
        float2 v0 = make_float2(acc[nt][0], acc[nt][1]);
        float2 v1 = make_float2(acc[nt][2], acc[nt][3]);
        if (add_src) {
            const float* ab = add_src + (size_t)b * M * NTOK;
            float2 a0 = *(const float2*)(ab + (size_t)r0 * NTOK + col);
            float2 a1 = *(const float2*)(ab + (size_t)(r0 + 8) * NTOK + col);
            v0.x += a0.x; v0.y += a0.y; v1.x += a1.x; v1.y += a1.y;
        }
        *(float2*)(Cb + (size_t)r0 * NTOK + col)       = v0;
        *(float2*)(Cb + (size_t)(r0 + 8) * NTOK + col) = v1;
    }
}

// ---------------- attention (mma.sync, chunked S, 12 warps/SM) -------------
#define ROWT 64
#define KS_LD 40
#define VT_LD 136

__global__ void __launch_bounds__(128, 3) attn_kernel()
{
    __shared__ __align__(16) __nv_bfloat16 Ks[128 * KS_LD];
    __shared__ __align__(16) __nv_bfloat16 Vt[DHEAD * VT_LD];
    __shared__ float pm_s [KCL * 128];
    __shared__ float pme_s[KCL * 128];

    const int t    = threadIdx.x;
    const int wid  = t >> 5;
    const int lane = t & 31;
    const int gid  = lane >> 2;
    const int q2   = (lane & 3) * 2;

    const int n0 = blockIdx.x * ROWT;
    const int h  = blockIdx.y;
    const int b  = blockIdx.z;

    const __nv_bfloat16* qh = g_qh + (size_t)(b * NHEAD + h) * NTOK * DHEAD;
    const __nv_bfloat16* kh = g_kh + (size_t)(b * NHEAD + h) * NTOK * DHEAD;
    const __nv_bfloat16* vh = g_vh + (size_t)(b * NHEAD + h) * DHEAD * NTOK;
    const float* pbase  = g_prob  + (size_t)b * KCL * NTOK;
    const float* pebase = g_probe + (size_t)b * KCL * NTOK;

    const int n_g = n0 + wid * 16 + gid;

    uint32_t qa[2][4];
#pragma unroll
    for (int kt = 0; kt < 2; kt++) {
        int d0 = kt * 16 + q2;
        qa[kt][0] = *(const uint32_t*)(qh + (size_t)n_g * DHEAD + d0);
        qa[kt][1] = *(const uint32_t*)(qh + (size_t)(n_g + 8) * DHEAD + d0);
        qa[kt][2] = *(const uint32_t*)(qh + (size_t)n_g * DHEAD + d0 + 8);
        qa[kt][3] = *(const uint32_t*)(qh + (size_t)(n_g + 8) * DHEAD + d0 + 8);
    }

    float pn0[KCL], pn1[KCL];
#pragma unroll
    for (int i = 0; i < KCL; i++) {
        pn0[i] = pbase[i * NTOK + n_g];
        pn1[i] = pbase[i * NTOK + n_g + 8];
    }

    float oacc[KCL][4][4];
    float lacc[KCL][2];
#pragma unroll
    for (int i = 0; i < KCL; i++) {
        lacc[i][0] = lacc[i][1] = 0.f;
#pragma unroll
        for (int dt = 0; dt < 4; dt++)
#pragma unroll
            for (int j = 0; j < 4; j++) oacc[i][dt][j] = 0.f;
    }

    for (int mt = 0; mt < NTOK; mt += 128) {
        __syncthreads();
        // stage K [m][d] (uint4), V^T [d][m] (uint4), pm/pme
#pragma unroll
        for (int i = 0; i < 4; i++) {
            int idx = t + i * 128;
            int row = idx >> 2, q = (idx & 3) * 8;
            *(uint4*)(Ks + row * KS_LD + q) =
                *(const uint4*)(kh + (size_t)(mt + row) * DHEAD + q);
        }
#pragma unroll
        for (int i = 0; i < 4; i++) {
            int idx = t + i * 128;
            int d = idx >> 4, q = (idx & 15) * 8;
            *(uint4*)(Vt + d * VT_LD + q) =
                *(const uint4*)(vh + (size_t)d * NTOK + mt + q);
        }
#pragma unroll
        for (int i = 0; i < 3; i++) {
            int idx = t + i * 128;
            int cl = idx >> 7, m = idx & 127;
            pm_s [cl * 128 + m] = pbase [(size_t)cl * NTOK + mt + m];
            pme_s[cl * 128 + m] = pebase[(size_t)cl * NTOK + mt + m];
        }
        __syncthreads();

#pragma unroll
        for (int chunk = 0; chunk < 4; chunk++) {
            const int c0 = chunk * 32;
            float sacc[4][4];
#pragma unroll
            for (int nt = 0; nt < 4; nt++) {
                sacc[nt][0] = sacc[nt][1] = sacc[nt][2] = sacc[nt][3] = 0.f;
                const __nv_bfloat16* kp = Ks + (c0 + nt * 8 + gid) * KS_LD;
                uint32_t b0 = *(const uint32_t*)(kp + q2);
                uint32_t b1 = *(const uint32_t*)(kp + q2 + 8);
                mma16816(sacc[nt], qa[0][0], qa[0][1], qa[0][2], qa[0][3], b0, b1);
                b0 = *(const uint32_t*)(kp + 16 + q2);
                b1 = *(const uint32_t*)(kp + 16 + q2 + 8);
                mma16816(sacc[nt], qa[1][0], qa[1][1], qa[1][2], qa[1][3], b0, b1);
            }

#pragma unroll
            for (int i = 0; i < KCL; i++) {
                const float cr0 = pn0[i], cr1 = pn1[i];
                const float* pmp  = pm_s  + i * 128 + c0;
                const float* pmep = pme_s + i * 128 + c0;
                float l0 = 0.f, l1 = 0.f;
#pragma unroll
                for (int s = 0; s < 2; s++) {
                    const float* pc  = pmp  + 16 * s;
                    const float* pce = pmep + 16 * s;
                    float pm00 = pc[q2],      pm01 = pc[q2 + 1];
                    float pm10 = pc[q2 + 8],  pm11 = pc[q2 + 9];
                    float pe00 = pce[q2],     pe01 = pce[q2 + 1];
                    float pe10 = pce[q2 + 8], pe11 = pce[q2 + 9];
                    const int j0 = 2 * s, j1 = 2 * s + 1;
                    float e00 = ex2f(sacc[j0][0] * cr0 * pe00);
                    float e01 = ex2f(sacc[j0][1] * cr0 * pe01);
                    float e02 = ex2f(sacc[j0][2] * cr1 * pe00);
                    float e03 = ex2f(sacc[j0][3] * cr1 * pe01);
                    float e10 = ex2f(sacc[j1][0] * cr0 * pe10);
                    float e11 = ex2f(sacc[j1][1] * cr0 * pe11);
                    float e12 = ex2f(sacc[j1][2] * cr1 * pe10);
                    float e13 = ex2f(sacc[j1][3] * cr1 * pe11);
                    l0 += e00 + e01 + e10 + e11;
                    l1 += e02 + e03 + e12 + e13;
                    uint32_t ra0 = packbf(e00 * pm00, e01 * pm01);
                    uint32_t ra1 = packbf(e02 * pm00, e03 * pm01);
                    uint32_t ra2 = packbf(e10 * pm10, e11 * pm11);
                    uint32_t ra3 = packbf(e12 * pm10, e13 * pm11);
#pragma unroll
                    for (int dt = 0; dt < 4; dt++) {
                        const __nv_bfloat16* vp = Vt + (dt * 8 + gid) * VT_LD + c0 + 16 * s;
                        uint32_t vb0 = *(const uint32_t*)(vp + q2);
                        uint32_t vb1 = *(const uint32_t*)(vp + q2 + 8);
                        mma16816(oacc[i][dt], ra0, ra1, ra2, ra3, vb0, vb1);
                    }
                }
                lacc[i][0] += l0;
                lacc[i][1] += l1;
            }
        }
    }

    float inv0[KCL], inv1[KCL];
#pragma unroll
    for (int i = 0; i < KCL; i++) {
        float l0 = lacc[i][0], l1 = lacc[i][1];
        l0 += __shfl_xor_sync(0xffffffffu, l0, 1);
        l0 += __shfl_xor_sync(0xffffffffu, l0, 2);
        l1 += __shfl_xor_sync(0xffffffffu, l1, 1);
        l1 += __shfl_xor_sync(0xffffffffu, l1, 2);
        inv0[i] = __fdividef(1.f, 3.f * l0);
        inv1[i] = __fdividef(1.f, 3.f * l1);
    }

    // write att^T bf16: [b][n][c], c = h*32 + d
    __nv_bfloat16* ob0 = g_attt + ((size_t)b * NTOK + n_g)     * C2D + h * DHEAD;
    __nv_bfloat16* ob1 = g_attt + ((size_t)b * NTOK + n_g + 8) * C2D + h * DHEAD;
#pragma unroll
    for (int dt = 0; dt < 4; dt++) {
        int d0 = dt * 8 + q2;
        float o00 = 0.f, o01 = 0.f, o10 = 0.f, o11 = 0.f;
#pragma unroll
        for (int i = 0; i < KCL; i++) {
            o00 += oacc[i][dt][0] * inv0[i];
            o01 += oacc[i][dt][1] * inv0[i];
            o10 += oacc[i][dt][2] * inv1[i];
            o11 += oacc[i][dt][3] * inv1[i];
        }
        *(uint32_t*)(ob0 + d0) = packbf(o00, o01);
        *(uint32_t*)(ob1 + d0) = packbf(o10, o11);
    }
}

// ---------------- fp32 GEMM for proj_in (identity precision) ---------------
__global__ __launch_bounds__(256) void gemm_bn(
    const float* __restrict__ A, const float* __restrict__ X,
    float* __restrict__ C, int M, int K)
{
    __shared__ float Asm[16][68];
    __shared__ float Bsm[16][68];

    const int b = blockIdx.z;
    const float* Xb = X + (size_t)b * K * NTOK;
    float* Cb = C + (size_t)b * M * NTOK;

    const int t  = threadIdx.x;
    const int tx = t & 15, ty = t >> 4;
    const int mblk = blockIdx.y * 64, nblk = blockIdx.x * 64;
    const int m0 = ty * 4, n0 = tx * 4;
    const int a_mm = t >> 2,  a_k4 = (t & 3) << 2;
    const int b_kk = t >> 4,  b_nn = (t & 15) << 2;

    float acc[4][4];
#pragma unroll
    for (int i = 0; i < 4; i++)
#pragma unroll
        for (int j = 0; j < 4; j++) acc[i][j] = 0.f;

    for (int kt = 0; kt < K; kt += 16) {
        __syncthreads();
        float4 av = *(const float4*)(A + (size_t)(mblk + a_mm) * K + kt + a_k4);
        Asm[a_k4 + 0][a_mm] = av.x;
        Asm[a_k4 + 1][a_mm] = av.y;
        Asm[a_k4 + 2][a_mm] = av.z;
        Asm[a_k4 + 3][a_mm] = av.w;
        *(float4*)(&Bsm[b_kk][b_nn]) =
            *(const float4*)(Xb + (size_t)(kt + b_kk) * NTOK + nblk + b_nn);
        __syncthreads();
#pragma unroll
        for (int kk = 0; kk < 16; kk++) {
            float4 a4 = *(const float4*)(&Asm[kk][m0]);
            float4 b4 = *(const float4*)(&Bsm[kk][n0]);
            float a[4]  = {a4.x, a4.y, a4.z, a4.w};
            float bb[4] = {b4.x, b4.y, b4.z, b4.w};
#pragma unroll
            for (int i = 0; i < 4; i++)
#pragma unroll
                for (int j = 0; j < 4; j++)
                    acc[i][j] = fmaf(a[i], bb[j], acc[i][j]);
        }
    }

#pragma unroll
    for (int i = 0; i < 4; i++) {
        size_t off = (size_t)(mblk + m0 + i) * NTOK + nblk + n0;
        *(float4*)(Cb + off) = make_float4(acc[i][0], acc[i][1], acc[i][2], acc[i][3]);
    }
}

// ---------------- converts -------------------------------------------------
__global__ __launch_bounds__(256) void conv_w(
    const float* __restrict__ Wq, const float* __restrict__ Wp)
{
    int idx = blockIdx.x * 256 + threadIdx.x;
    if (idx < 3 * C2D * C2D) g_wqh[idx] = __float2bfloat16(Wq[idx]);
    else {
        int j = idx - 3 * C2D * C2D;
        if (j < C2D * C2D) g_wph[j] = __float2bfloat16(Wp[j]);
    }
}

__global__ __launch_bounds__(128) void conv_xf()
{
    const int n = blockIdx.x * 128 + threadIdx.x;
    const int b = blockIdx.y;
    const float* src = g_xf + (size_t)b * C2D * NTOK + n;
    __nv_bfloat16* dst = g_xft + ((size_t)b * NTOK + n) * C2D;
#pragma unroll
    for (int k0 = 0; k0 < C2D; k0 += 8) {
        uint4 w;
        w.x = packbf(src[(size_t)(k0    ) * NTOK], src[(size_t)(k0 + 1) * NTOK]);
        w.y = packbf(src[(size_t)(k0 + 2) * NTOK], src[(size_t)(k0 + 3) * NTOK]);
        w.z = packbf(src[(size_t)(k0 + 4) * NTOK], src[(size_t)(k0 + 5) * NTOK]);
        w.w = packbf(src[(size_t)(k0 + 6) * NTOK], src[(size_t)(k0 + 7) * NTOK]);
        *(uint4*)(dst + k0) = w;
    }
}

__global__ __launch_bounds__(128) void conv_qkv()
{
    const int n = blockIdx.x * 128 + threadIdx.x;
    const int h = blockIdx.y, b = blockIdx.z;
    const float* qb = g_qkv + ((size_t)b * 3 * C2D + h * DHEAD) * NTOK + n;
    const float* kb = qb + (size_t)C2D * NTOK;
    const float* vb = qb + (size_t)2 * C2D * NTOK;
    __nv_bfloat16* qo = g_qh + ((size_t)(b * NHEAD + h) * NTOK + n) * DHEAD;
    __nv_bfloat16* ko = g_kh + ((size_t)(b * NHEAD + h) * NTOK + n) * DHEAD;
    __nv_bfloat16* vo = g_vh + (size_t)(b * NHEAD + h) * DHEAD * NTOK + n;

    uint32_t buf[16];
#pragma unroll
    for (int j = 0; j < 16; j++)
        buf[j] = packbf(qb[(size_t)(2 * j) * NTOK], qb[(size_t)(2 * j + 1) * NTOK]);
#pragma unroll
    for (int j = 0; j < 4; j++) *(uint4*)(qo + j * 8) = *(uint4*)(buf + j * 4);
#pragma unroll
    for (int j = 0; j < 16; j++)
        buf[j] = packbf(kb[(size_t)(2 * j) * NTOK], kb[(size_t)(2 * j + 1) * NTOK]);
#pragma unroll
    for (int j = 0; j < 4; j++) *(uint4*)(ko + j * 8) = *(uint4*)(buf + j * 4);
#pragma unroll
    for (int d = 0; d < DHEAD; d++)
        vo[(size_t)d * NTOK] = __float2bfloat16(vb[(size_t)d * NTOK]);
}

// ---------------- cluster probs --------------------------------------------
__global__ __launch_bounds__(256) void prob_kernel(
    const float* __restrict__ Wc, const float* __restrict__ bc)
{
    __shared__ float W[KCL * C2D];
    __shared__ float bias[KCL];
    const int t = threadIdx.x;
    for (int i = t; i < KCL * C2D; i += 256) W[i] = Wc[i];
    if (t < KCL) bias[t] = bc[t];
    __syncthreads();

    const int gidx = blockIdx.x * 256 + t;
    const int b = gidx >> 10, n = gidx & 1023;
    float l0 = bias[0], l1 = bias[1], l2 = bias[2];
    const float* xb = g_xf + (size_t)b * C2D * NTOK + n;
#pragma unroll 4
    for (int c = 0; c < C2D; c++) {
        float xv = xb[(size_t)c * NTOK];
        l0 = fmaf(W[c],           xv, l0);
        l1 = fmaf(W[C2D + c],     xv, l1);
        l2 = fmaf(W[2 * C2D + c], xv, l2);
    }
    float mx = fmaxf(l0, fmaxf(l1, l2));
    float e0 = __expf(l0 - mx), e1 = __expf(l1 - mx), e2 = __expf(l2 - mx);
    float inv = 1.f / (e0 + e1 + e2);
    float p0 = e0 * inv, p1 = e1 * inv, p2 = e2 * inv;
    float* pb  = g_prob  + (size_t)b * KCL * NTOK + n;
    float* peb = g_probe + (size_t)b * KCL * NTOK + n;
    pb[0]        = p0;  peb[0]        = p0 * EXPSC;
    pb[NTOK]     = p1;  peb[NTOK]     = p1 * EXPSC;
    pb[2 * NTOK] = p2;  peb[2 * NTOK] = p2 * EXPSC;
}

// ---------------- launch ---------------------------------------------------
extern "C" void kernel_launch(void* const* d_in, const int* in_sizes, int n_in,
                              void* d_out, int out_size)
{
    const float* x      = (const float*)d_in[0];
    const float* W_in   = (const float*)d_in[1];
    const float* Wc     = (const float*)d_in[2];
    const float* bc     = (const float*)d_in[3];
    const float* W_qkv  = (const float*)d_in[4];
    const float* W_proj = (const float*)d_in[5];
    float* out = (float*)d_out;

    float *xf, *qkv;
    __nv_bfloat16 *wqh, *wph, *xft, *attt;
    cudaGetSymbolAddress((void**)&xf,   g_xf);
    cudaGetSymbolAddress((void**)&qkv,  g_qkv);
    cudaGetSymbolAddress((void**)&wqh,  g_wqh);
    cudaGetSymbolAddress((void**)&wph,  g_wph);
    cudaGetSymbolAddress((void**)&xft,  g_xft);
    cudaGetSymbolAddress((void**)&attt, g_attt);

    cudaFuncSetAttribute(gemm_h,
        cudaFuncAttributeMaxDynamicSharedMemorySize, GEMMH_SMEM);

    // 1) xf = W_in @ x  (fp32, identity path stays exact)
    gemm_bn<<<dim3(16, 4, BDIM), 256>>>(W_in, x, xf, 256, 128);
    // 2) weight + xf^T bf16 conversions, cluster probs
    conv_w<<<1024, 256>>>(W_qkv, W_proj);
    conv_xf<<<dim3(8, BDIM), 128>>>();
    prob_kernel<<<(BDIM * NTOK) / 256, 256>>>(Wc, bc);
    // 3) qkv = W_qkv @ xf (bf16 tensor cores)
    gemm_h<<<dim3(16, 12, BDIM), 128, GEMMH_SMEM>>>(wqh, xft, qkv, nullptr, 768);
    // 4) qkv -> bf16 attention layouts
    conv_qkv<<<dim3(8, NHEAD, BDIM), 128>>>();
    // 5) clustered attention
    attn_kernel<<<dim3(NTOK / ROWT, NHEAD, BDIM), 128>>>();
    // 6) out = W_proj @ att + xf (bf16 tensor cores, fp32 identity add)
    gemm_h<<<dim3(16, 4, BDIM), 128, GEMMH_SMEM>>>(wph, attt, out, xf, 256);
}

// round 10
// speedup vs baseline: 3.9982x; 1.1435x over previous
#include <cuda_runtime.h>
#include <cuda_bf16.h>
#include <math.h>
#include <stdint.h>

#define BDIM  8
#define C2D   256
#define NTOK  1024
#define NHEAD 8
#define DHEAD 32
#define KCL   3
#define QKSCALE 0.17677669529663687f
#define EXPSC  (0.17677669529663687f * 1.4426950408889634f)

// ---------------- scratch ----------------
__device__ float g_xf  [BDIM * C2D * NTOK];            // fp32 proj_in (identity)
__device__ float g_qkv [BDIM * 3 * C2D * NTOK];        // fp32 qkv
__device__ float g_prob[BDIM * KCL * NTOK];            // raw probs
__device__ float g_probe[BDIM * KCL * NTOK];           // probs * SCALE*log2e
__device__ __nv_bfloat16 g_wqh [3 * C2D * C2D];        // W_qkv bf16
__device__ __nv_bfloat16 g_wph [C2D * C2D];            // W_proj bf16
__device__ __nv_bfloat16 g_xft [BDIM * NTOK * C2D];    // xf^T bf16 [b][n][k]
__device__ __nv_bfloat16 g_qh  [BDIM * NHEAD * NTOK * DHEAD]; // [b][h][n][d]
__device__ __nv_bfloat16 g_kh  [BDIM * NHEAD * NTOK * DHEAD]; // [b][h][m][d]
__device__ __nv_bfloat16 g_vh  [BDIM * NHEAD * DHEAD * NTOK]; // [b][h][d][m]
__device__ __nv_bfloat16 g_attt[BDIM * NTOK * C2D];    // attn out^T bf16 [b][n][c]

// ---------------- helpers ----------------
__device__ __forceinline__ void mma16816(float* d,
    uint32_t a0, uint32_t a1, uint32_t a2, uint32_t a3,
    uint32_t b0, uint32_t b1)
{
    asm volatile(
        "mma.sync.aligned.m16n8k16.row.col.f32.bf16.bf16.f32 "
        "{%0,%1,%2,%3}, {%4,%5,%6,%7}, {%8,%9}, {%0,%1,%2,%3};"
        : "+f"(d[0]), "+f"(d[1]), "+f"(d[2]), "+f"(d[3])
        : "r"(a0), "r"(a1), "r"(a2), "r"(a3), "r"(b0), "r"(b1));
}
__device__ __forceinline__ uint32_t packbf(float lo, float hi) {
    __nv_bfloat162 p = __floats2bfloat162_rn(lo, hi);
    return *(uint32_t*)&p;
}
__device__ __forceinline__ float ex2f(float x) {
    float r; asm("ex2.approx.ftz.f32 %0, %1;" : "=f"(r) : "f"(x)); return r;
}
__device__ __forceinline__ float bflo(uint32_t u) { return __uint_as_float(u << 16); }
__device__ __forceinline__ float bfhi(uint32_t u) { return __uint_as_float(u & 0xffff0000u); }

// ---------------- bf16 GEMM: C[b] = A @ Xt[b]^T (+add) ---------------------
#define GK 256
#define GLD 264
#define GEMMH_SMEM (2 * 64 * GLD * 2)
__global__ __launch_bounds__(128) void gemm_h(
    const __nv_bfloat16* __restrict__ Ah, const __nv_bfloat16* __restrict__ Xt,
    float* __restrict__ C, const float* __restrict__ add_src, int M)
{
    extern __shared__ __nv_bfloat16 gs[];
    __nv_bfloat16* As = gs;
    __nv_bfloat16* Bs = gs + 64 * GLD;

    const int t = threadIdx.x;
    const int lane = t & 31, wid = t >> 5;
    const int gid = lane >> 2, q2 = (lane & 3) * 2;
    const int mblk = blockIdx.y * 64, nblk = blockIdx.x * 64, b = blockIdx.z;

    const __nv_bfloat16* Xb = Xt + ((size_t)b * NTOK + nblk) * GK;
#pragma unroll
    for (int i = 0; i < 16; i++) {
        int idx = t + i * 128;
        int row = idx >> 5, q = (idx & 31) * 8;
        *(uint4*)(As + row * GLD + q) = *(const uint4*)(Ah + (size_t)(mblk + row) * GK + q);
        *(uint4*)(Bs + row * GLD + q) = *(const uint4*)(Xb + (size_t)row * GK + q);
    }
    __syncthreads();

    const int wm = wid * 16;
    float acc[8][4];
#pragma unroll
    for (int nt = 0; nt < 8; nt++)
#pragma unroll
        for (int j = 0; j < 4; j++) acc[nt][j] = 0.f;

#pragma unroll
    for (int kt = 0; kt < GK / 16; kt++) {
        const int ka = kt * 16 + q2;
        uint32_t a0 = *(const uint32_t*)(As + (wm + gid) * GLD + ka);
        uint32_t a1 = *(const uint32_t*)(As + (wm + gid + 8) * GLD + ka);
        uint32_t a2 = *(const uint32_t*)(As + (wm + gid) * GLD + ka + 8);
        uint32_t a3 = *(const uint32_t*)(As + (wm + gid + 8) * GLD + ka + 8);
#pragma unroll
        for (int nt = 0; nt < 8; nt++) {
            uint32_t b0 = *(const uint32_t*)(Bs + (nt * 8 + gid) * GLD + ka);
            uint32_t b1 = *(const uint32_t*)(Bs + (nt * 8 + gid) * GLD + ka + 8);
            mma16816(acc[nt], a0, a1, a2, a3, b0, b1);
        }
    }

    float* Cb = C + (size_t)b * M * NTOK;
    const int r0 = mblk + wm + gid;
#pragma unroll
    for (int nt = 0; nt < 8; nt++) {
        int col = nblk + nt * 8 + q2;
        float2 v0 = make_float2(acc[nt][0], acc[nt][1]);
        float2 v1 = make_float2(acc[nt][2], acc[nt][3]);
        if (add_src) {
            const float* ab = add_src + (size_t)b * M * NTOK;
            float2 a0 = *(const float2*)(ab + (size_t)r0 * NTOK + col);
            float2 a1 = *(const float2*)(ab + (size_t)(r0 + 8) * NTOK + col);
            v0.x += a0.x; v0.y += a0.y; v1.x += a1.x; v1.y += a1.y;
        }
        *(float2*)(Cb + (size_t)r0 * NTOK + col)       = v0;
        *(float2*)(Cb + (size_t)(r0 + 8) * NTOK + col) = v1;
    }
}

// ---------------- attention (mma.sync, chunked S) --------------------------
#define ROWT 64
#define KS_LD 40
#define VT_LD 136

__global__ void __launch_bounds__(128, 4) attn_kernel()
{
    __shared__ __align__(16) __nv_bfloat16 Ks[128 * KS_LD];
    __shared__ __align__(16) __nv_bfloat16 Vt[DHEAD * VT_LD];
    __shared__ float pm_s [KCL * 128];
    __shared__ float pme_s[KCL * 128];

    const int t    = threadIdx.x;
    const int wid  = t >> 5;
    const int lane = t & 31;
    const int gid  = lane >> 2;
    const int q2   = (lane & 3) * 2;

    const int n0 = blockIdx.x * ROWT;
    const int h  = blockIdx.y;
    const int b  = blockIdx.z;

    const __nv_bfloat16* qh = g_qh + (size_t)(b * NHEAD + h) * NTOK * DHEAD;
    const __nv_bfloat16* kh = g_kh + (size_t)(b * NHEAD + h) * NTOK * DHEAD;
    const __nv_bfloat16* vh = g_vh + (size_t)(b * NHEAD + h) * DHEAD * NTOK;
    const float* pbase  = g_prob  + (size_t)b * KCL * NTOK;
    const float* pebase = g_probe + (size_t)b * KCL * NTOK;

    const int n_g = n0 + wid * 16 + gid;

    uint32_t qa[2][4];
#pragma unroll
    for (int kt = 0; kt < 2; kt++) {
        int d0 = kt * 16 + q2;
        qa[kt][0] = *(const uint32_t*)(qh + (size_t)n_g * DHEAD + d0);
        qa[kt][1] = *(const uint32_t*)(qh + (size_t)(n_g + 8) * DHEAD + d0);
        qa[kt][2] = *(const uint32_t*)(qh + (size_t)n_g * DHEAD + d0 + 8);
        qa[kt][3] = *(const uint32_t*)(qh + (size_t)(n_g + 8) * DHEAD + d0 + 8);
    }

    float pn0[KCL], pn1[KCL];
#pragma unroll
    for (int i = 0; i < KCL; i++) {
        pn0[i] = pbase[i * NTOK + n_g];
        pn1[i] = pbase[i * NTOK + n_g + 8];
    }

    float oacc[KCL][4][4];
    float lacc[KCL][2];
#pragma unroll
    for (int i = 0; i < KCL; i++) {
        lacc[i][0] = lacc[i][1] = 0.f;
#pragma unroll
        for (int dt = 0; dt < 4; dt++)
#pragma unroll
            for (int j = 0; j < 4; j++) oacc[i][dt][j] = 0.f;
    }

    for (int mt = 0; mt < NTOK; mt += 128) {
        __syncthreads();
#pragma unroll
        for (int i = 0; i < 4; i++) {
            int idx = t + i * 128;
            int row = idx >> 2, q = (idx & 3) * 8;
            *(uint4*)(Ks + row * KS_LD + q) =
                *(const uint4*)(kh + (size_t)(mt + row) * DHEAD + q);
        }
#pragma unroll
        for (int i = 0; i < 4; i++) {
            int idx = t + i * 128;
            int d = idx >> 4, q = (idx & 15) * 8;
            *(uint4*)(Vt + d * VT_LD + q) =
                *(const uint4*)(vh + (size_t)d * NTOK + mt + q);
        }
#pragma unroll
        for (int i = 0; i < 3; i++) {
            int idx = t + i * 128;
            int cl = idx >> 7, m = idx & 127;
            pm_s [cl * 128 + m] = pbase [(size_t)cl * NTOK + mt + m];
            pme_s[cl * 128 + m] = pebase[(size_t)cl * NTOK + mt + m];
        }
        __syncthreads();

#pragma unroll
        for (int chunk = 0; chunk < 4; chunk++) {
            const int c0 = chunk * 32;
            float sacc[4][4];
#pragma unroll
            for (int nt = 0; nt < 4; nt++) {
                sacc[nt][0] = sacc[nt][1] = sacc[nt][2] = sacc[nt][3] = 0.f;
                const __nv_bfloat16* kp = Ks + (c0 + nt * 8 + gid) * KS_LD;
                uint32_t b0 = *(const uint32_t*)(kp + q2);
                uint32_t b1 = *(const uint32_t*)(kp + q2 + 8);
                mma16816(sacc[nt], qa[0][0], qa[0][1], qa[0][2], qa[0][3], b0, b1);
                b0 = *(const uint32_t*)(kp + 16 + q2);
                b1 = *(const uint32_t*)(kp + 16 + q2 + 8);
                mma16816(sacc[nt], qa[1][0], qa[1][1], qa[1][2], qa[1][3], b0, b1);
            }

#pragma unroll
            for (int i = 0; i < KCL; i++) {
                const float cr0 = pn0[i], cr1 = pn1[i];
                const float* pmp  = pm_s  + i * 128 + c0;
                const float* pmep = pme_s + i * 128 + c0;
                float l0 = 0.f, l1 = 0.f;
#pragma unroll
                for (int s = 0; s < 2; s++) {
                    const float* pc  = pmp  + 16 * s;
                    const float* pce = pmep + 16 * s;
                    float pm00 = pc[q2],      pm01 = pc[q2 + 1];
                    float pm10 = pc[q2 + 8],  pm11 = pc[q2 + 9];
                    float pe00 = pce[q2],     pe01 = pce[q2 + 1];
                    float pe10 = pce[q2 + 8], pe11 = pce[q2 + 9];
                    const int j0 = 2 * s, j1 = 2 * s + 1;
                    float e00 = ex2f(sacc[j0][0] * cr0 * pe00);
                    float e01 = ex2f(sacc[j0][1] * cr0 * pe01);
                    float e02 = ex2f(sacc[j0][2] * cr1 * pe00);
                    float e03 = ex2f(sacc[j0][3] * cr1 * pe01);
                    float e10 = ex2f(sacc[j1][0] * cr0 * pe10);
                    float e11 = ex2f(sacc[j1][1] * cr0 * pe11);
                    float e12 = ex2f(sacc[j1][2] * cr1 * pe10);
                    float e13 = ex2f(sacc[j1][3] * cr1 * pe11);
                    l0 += e00 + e01 + e10 + e11;
                    l1 += e02 + e03 + e12 + e13;
                    uint32_t ra0 = packbf(e00 * pm00, e01 * pm01);
                    uint32_t ra1 = packbf(e02 * pm00, e03 * pm01);
                    uint32_t ra2 = packbf(e10 * pm10, e11 * pm11);
                    uint32_t ra3 = packbf(e12 * pm10, e13 * pm11);
#pragma unroll
                    for (int dt = 0; dt < 4; dt++) {
                        const __nv_bfloat16* vp = Vt + (dt * 8 + gid) * VT_LD + c0 + 16 * s;
                        uint32_t vb0 = *(const uint32_t*)(vp + q2);
                        uint32_t vb1 = *(const uint32_t*)(vp + q2 + 8);
                        mma16816(oacc[i][dt], ra0, ra1, ra2, ra3, vb0, vb1);
                    }
                }
                lacc[i][0] += l0;
                lacc[i][1] += l1;
            }
        }
    }

    float inv0[KCL], inv1[KCL];
#pragma unroll
    for (int i = 0; i < KCL; i++) {
        float l0 = lacc[i][0], l1 = lacc[i][1];
        l0 += __shfl_xor_sync(0xffffffffu, l0, 1);
        l0 += __shfl_xor_sync(0xffffffffu, l0, 2);
        l1 += __shfl_xor_sync(0xffffffffu, l1, 1);
        l1 += __shfl_xor_sync(0xffffffffu, l1, 2);
        inv0[i] = __fdividef(1.f, 3.f * l0);
        inv1[i] = __fdividef(1.f, 3.f * l1);
    }

    __nv_bfloat16* ob0 = g_attt + ((size_t)b * NTOK + n_g)     * C2D + h * DHEAD;
    __nv_bfloat16* ob1 = g_attt + ((size_t)b * NTOK + n_g + 8) * C2D + h * DHEAD;
#pragma unroll
    for (int dt = 0; dt < 4; dt++) {
        int d0 = dt * 8 + q2;
        float o00 = 0.f, o01 = 0.f, o10 = 0.f, o11 = 0.f;
#pragma unroll
        for (int i = 0; i < KCL; i++) {
            o00 += oacc[i][dt][0] * inv0[i];
            o01 += oacc[i][dt][1] * inv0[i];
            o10 += oacc[i][dt][2] * inv1[i];
            o11 += oacc[i][dt][3] * inv1[i];
        }
        *(uint32_t*)(ob0 + d0) = packbf(o00, o01);
        *(uint32_t*)(ob1 + d0) = packbf(o10, o11);
    }
}

// ---------------- fp32 GEMM for proj_in + fused bf16 transpose -------------
__global__ __launch_bounds__(256) void gemm_bn(
    const float* __restrict__ A, const float* __restrict__ X,
    float* __restrict__ C, int M, int K)
{
    __shared__ float Asm[16][68];
    __shared__ float Bsm[16][68];

    const int b = blockIdx.z;
    const float* Xb = X + (size_t)b * K * NTOK;
    float* Cb = C + (size_t)b * M * NTOK;

    const int t  = threadIdx.x;
    const int tx = t & 15, ty = t >> 4;
    const int mblk = blockIdx.y * 64, nblk = blockIdx.x * 64;
    const int m0 = ty * 4, n0 = tx * 4;
    const int a_mm = t >> 2,  a_k4 = (t & 3) << 2;
    const int b_kk = t >> 4,  b_nn = (t & 15) << 2;

    float acc[4][4];
#pragma unroll
    for (int i = 0; i < 4; i++)
#pragma unroll
        for (int j = 0; j < 4; j++) acc[i][j] = 0.f;

    for (int kt = 0; kt < K; kt += 16) {
        __syncthreads();
        float4 av = *(const float4*)(A + (size_t)(mblk + a_mm) * K + kt + a_k4);
        Asm[a_k4 + 0][a_mm] = av.x;
        Asm[a_k4 + 1][a_mm] = av.y;
        Asm[a_k4 + 2][a_mm] = av.z;
        Asm[a_k4 + 3][a_mm] = av.w;
        *(float4*)(&Bsm[b_kk][b_nn]) =
            *(const float4*)(Xb + (size_t)(kt + b_kk) * NTOK + nblk + b_nn);
        __syncthreads();
#pragma unroll
        for (int kk = 0; kk < 16; kk++) {
            float4 a4 = *(const float4*)(&Asm[kk][m0]);
            float4 b4 = *(const float4*)(&Bsm[kk][n0]);
            float a[4]  = {a4.x, a4.y, a4.z, a4.w};
            float bb[4] = {b4.x, b4.y, b4.z, b4.w};
#pragma unroll
            for (int i = 0; i < 4; i++)
#pragma unroll
                for (int j = 0; j < 4; j++)
                    acc[i][j] = fmaf(a[i], bb[j], acc[i][j]);
        }
    }

#pragma unroll
    for (int i = 0; i < 4; i++) {
        size_t off = (size_t)(mblk + m0 + i) * NTOK + nblk + n0;
        *(float4*)(Cb + off) = make_float4(acc[i][0], acc[i][1], acc[i][2], acc[i][3]);
    }
    // fused transpose: xft[b][n][c] bf16
    __nv_bfloat16* xtb = g_xft + (size_t)b * NTOK * C2D;
#pragma unroll
    for (int j = 0; j < 4; j++) {
        __nv_bfloat16* dst = xtb + (size_t)(nblk + n0 + j) * C2D + mblk + m0;
        *(uint32_t*)(dst)     = packbf(acc[0][j], acc[1][j]);
        *(uint32_t*)(dst + 2) = packbf(acc[2][j], acc[3][j]);
    }
}

// ---------------- converts -------------------------------------------------
__global__ __launch_bounds__(256) void conv_w(
    const float* __restrict__ Wq, const float* __restrict__ Wp)
{
    int idx = blockIdx.x * 256 + threadIdx.x;
    if (idx < 3 * C2D * C2D) g_wqh[idx] = __float2bfloat16(Wq[idx]);
    else {
        int j = idx - 3 * C2D * C2D;
        if (j < C2D * C2D) g_wph[j] = __float2bfloat16(Wp[j]);
    }
}

__global__ __launch_bounds__(128) void conv_qkv()
{
    const int n = blockIdx.x * 128 + threadIdx.x;
    const int h = blockIdx.y, b = blockIdx.z;
    const float* qb = g_qkv + ((size_t)b * 3 * C2D + h * DHEAD) * NTOK + n;
    const float* kb = qb + (size_t)C2D * NTOK;
    const float* vb = qb + (size_t)2 * C2D * NTOK;
    __nv_bfloat16* qo = g_qh + ((size_t)(b * NHEAD + h) * NTOK + n) * DHEAD;
    __nv_bfloat16* ko = g_kh + ((size_t)(b * NHEAD + h) * NTOK + n) * DHEAD;
    __nv_bfloat16* vo = g_vh + (size_t)(b * NHEAD + h) * DHEAD * NTOK + n;

    uint32_t buf[16];
#pragma unroll
    for (int j = 0; j < 16; j++)
        buf[j] = packbf(qb[(size_t)(2 * j) * NTOK], qb[(size_t)(2 * j + 1) * NTOK]);
#pragma unroll
    for (int j = 0; j < 4; j++) *(uint4*)(qo + j * 8) = *(uint4*)(buf + j * 4);
#pragma unroll
    for (int j = 0; j < 16; j++)
        buf[j] = packbf(kb[(size_t)(2 * j) * NTOK], kb[(size_t)(2 * j + 1) * NTOK]);
#pragma unroll
    for (int j = 0; j < 4; j++) *(uint4*)(ko + j * 8) = *(uint4*)(buf + j * 4);
#pragma unroll
    for (int d = 0; d < DHEAD; d++)
        vo[(size_t)d * NTOK] = __float2bfloat16(vb[(size_t)d * NTOK]);
}

// ---------------- cluster probs (bf16 xft, 4 threads/token) ----------------
__global__ __launch_bounds__(256) void prob_kernel(
    const float* __restrict__ Wc, const float* __restrict__ bc)
{
    __shared__ float W[KCL * C2D];
    __shared__ float bias[KCL];
    const int t = threadIdx.x;
    for (int i = t; i < KCL * C2D; i += 256) W[i] = Wc[i];
    if (t < KCL) bias[t] = bc[t];
    __syncthreads();

    const int gidx = blockIdx.x * 256 + t;
    const int tok = gidx >> 2;
    const int p   = t & 3;
    const int b = tok >> 10, n = tok & 1023;

    const __nv_bfloat16* xp = g_xft + ((size_t)(b * NTOK + n)) * C2D + p * 64;
    const float* W0 = W + p * 64;
    float l0 = 0.f, l1 = 0.f, l2 = 0.f;
#pragma unroll
    for (int j = 0; j < 8; j++) {
        uint4 v = *(const uint4*)(xp + j * 8);
        const float* w = W0 + j * 8;
        float x0 = bflo(v.x), x1 = bfhi(v.x);
        float x2 = bflo(v.y), x3 = bfhi(v.y);
        float x4 = bflo(v.z), x5 = bfhi(v.z);
        float x6 = bflo(v.w), x7 = bfhi(v.w);
        l0 = fmaf(w[0], x0, l0); l0 = fmaf(w[1], x1, l0);
        l0 = fmaf(w[2], x2, l0); l0 = fmaf(w[3], x3, l0);
        l0 = fmaf(w[4], x4, l0); l0 = fmaf(w[5], x5, l0);
        l0 = fmaf(w[6], x6, l0); l0 = fmaf(w[7], x7, l0);
        l1 = fmaf(w[C2D + 0], x0, l1); l1 = fmaf(w[C2D + 1], x1, l1);
        l1 = fmaf(w[C2D + 2], x2, l1); l1 = fmaf(w[C2D + 3], x3, l1);
        l1 = fmaf(w[C2D + 4], x4, l1); l1 = fmaf(w[C2D + 5], x5, l1);
        l1 = fmaf(w[C2D + 6], x6, l1); l1 = fmaf(w[C2D + 7], x7, l1);
        l2 = fmaf(w[2 * C2D + 0], x0, l2); l2 = fmaf(w[2 * C2D + 1], x1, l2);
        l2 = fmaf(w[2 * C2D + 2], x2, l2); l2 = fmaf(w[2 * C2D + 3], x3, l2);
        l2 = fmaf(w[2 * C2D + 4], x4, l2); l2 = fmaf(w[2 * C2D + 5], x5, l2);
        l2 = fmaf(w[2 * C2D + 6], x6, l2); l2 = fmaf(w[2 * C2D + 7], x7, l2);
    }
    l0 += __shfl_xor_sync(0xffffffffu, l0, 1);
    l0 += __shfl_xor_sync(0xffffffffu, l0, 2);
    l1 += __shfl_xor_sync(0xffffffffu, l1, 1);
    l1 += __shfl_xor_sync(0xffffffffu, l1, 2);
    l2 += __shfl_xor_sync(0xffffffffu, l2, 1);
    l2 += __shfl_xor_sync(0xffffffffu, l2, 2);

    if (p == 0) {
        l0 += bias[0]; l1 += bias[1]; l2 += bias[2];
        float mx = fmaxf(l0, fmaxf(l1, l2));
        float e0 = __expf(l0 - mx), e1 = __expf(l1 - mx), e2 = __expf(l2 - mx);
        float inv = 1.f / (e0 + e1 + e2);
        float p0 = e0 * inv, p1 = e1 * inv, p2 = e2 * inv;
        float* pb  = g_prob  + (size_t)b * KCL * NTOK + n;
        float* peb = g_probe + (size_t)b * KCL * NTOK + n;
        pb[0]        = p0;  peb[0]        = p0 * EXPSC;
        pb[NTOK]     = p1;  peb[NTOK]     = p1 * EXPSC;
        pb[2 * NTOK] = p2;  peb[2 * NTOK] = p2 * EXPSC;
    }
}

// ---------------- launch ---------------------------------------------------
extern "C" void kernel_launch(void* const* d_in, const int* in_sizes, int n_in,
                              void* d_out, int out_size)
{
    const float* x      = (const float*)d_in[0];
    const float* W_in   = (const float*)d_in[1];
    const float* Wc     = (const float*)d_in[2];
    const float* bc     = (const float*)d_in[3];
    const float* W_qkv  = (const float*)d_in[4];
    const float* W_proj = (const float*)d_in[5];
    float* out = (float*)d_out;

    float *xf, *qkv;
    __nv_bfloat16 *wqh, *wph, *xft, *attt;
    cudaGetSymbolAddress((void**)&xf,   g_xf);
    cudaGetSymbolAddress((void**)&qkv,  g_qkv);
    cudaGetSymbolAddress((void**)&wqh,  g_wqh);
    cudaGetSymbolAddress((void**)&wph,  g_wph);
    cudaGetSymbolAddress((void**)&xft,  g_xft);
    cudaGetSymbolAddress((void**)&attt, g_attt);

    cudaFuncSetAttribute(gemm_h,
        cudaFuncAttributeMaxDynamicSharedMemorySize, GEMMH_SMEM);

    // 1) xf = W_in @ x  (fp32) + fused bf16 transpose to xft
    gemm_bn<<<dim3(16, 4, BDIM), 256>>>(W_in, x, xf, 256, 128);
    // 2) weight conversions + cluster probs (from xft)
    conv_w<<<1024, 256>>>(W_qkv, W_proj);
    prob_kernel<<<(BDIM * NTOK * 4) / 256, 256>>>(Wc, bc);
    // 3) qkv = W_qkv @ xf (bf16 tensor cores)
    gemm_h<<<dim3(16, 12, BDIM), 128, GEMMH_SMEM>>>(wqh, xft, qkv, nullptr, 768);
    // 4) qkv -> bf16 attention layouts
    conv_qkv<<<dim3(8, NHEAD, BDIM), 128>>>();
    // 5) clustered attention
    attn_kernel<<<dim3(NTOK / ROWT, NHEAD, BDIM), 128>>>();
    // 6) out = W_proj @ att + xf (bf16 tensor cores, fp32 identity add)
    gemm_h<<<dim3(16, 4, BDIM), 128, GEMMH_SMEM>>>(wph, attt, out, xf, 256);
}

// round 11
// speedup vs baseline: 7.1374x; 1.7851x over previous
#include <cuda_runtime.h>
#include <cuda_bf16.h>
#include <math.h>
#include <stdint.h>

#define BDIM  8
#define C2D   256
#define NTOK  1024
#define NHEAD 8
#define DHEAD 32
#define KCL   3
#define QKSCALE 0.17677669529663687f
#define EXPSC  (0.17677669529663687f * 1.4426950408889634f)

// ---------------- scratch ----------------
__device__ float g_xf  [BDIM * C2D * NTOK];            // fp32 proj_in (identity)
__device__ float g_prob[BDIM * KCL * NTOK];
__device__ float g_probe[BDIM * KCL * NTOK];
__device__ __nv_bfloat16 g_wqh [3 * C2D * C2D];
__device__ __nv_bfloat16 g_wph [C2D * C2D];
__device__ __nv_bfloat16 g_xft [BDIM * NTOK * C2D];    // xf^T bf16 [b][n][k]
__device__ __nv_bfloat16 g_qh  [BDIM * NHEAD * NTOK * DHEAD]; // [b][h][n][d]
__device__ __nv_bfloat16 g_kh  [BDIM * NHEAD * NTOK * DHEAD]; // [b][h][m][d]
__device__ __nv_bfloat16 g_vh  [BDIM * NHEAD * DHEAD * NTOK]; // [b][h][d][m]
__device__ __nv_bfloat16 g_attt[BDIM * NTOK * C2D];    // attn out^T bf16 [b][n][c]

// ---------------- helpers ----------------
__device__ __forceinline__ uint32_t smem_u32(const void* p) {
    uint32_t a;
    asm("{ .reg .u64 t; cvta.to.shared.u64 t, %1; cvt.u32.u64 %0, t; }" : "=r"(a) : "l"(p));
    return a;
}
__device__ __forceinline__ void mma16816(float* d,
    uint32_t a0, uint32_t a1, uint32_t a2, uint32_t a3,
    uint32_t b0, uint32_t b1)
{
    asm volatile(
        "mma.sync.aligned.m16n8k16.row.col.f32.bf16.bf16.f32 "
        "{%0,%1,%2,%3}, {%4,%5,%6,%7}, {%8,%9}, {%0,%1,%2,%3};"
        : "+f"(d[0]), "+f"(d[1]), "+f"(d[2]), "+f"(d[3])
        : "r"(a0), "r"(a1), "r"(a2), "r"(a3), "r"(b0), "r"(b1));
}
__device__ __forceinline__ void mma1688tf(float* d,
    uint32_t a0, uint32_t a1, uint32_t a2, uint32_t a3,
    uint32_t b0, uint32_t b1)
{
    asm volatile(
        "mma.sync.aligned.m16n8k8.row.col.f32.tf32.tf32.f32 "
        "{%0,%1,%2,%3}, {%4,%5,%6,%7}, {%8,%9}, {%0,%1,%2,%3};"
        : "+f"(d[0]), "+f"(d[1]), "+f"(d[2]), "+f"(d[3])
        : "r"(a0), "r"(a1), "r"(a2), "r"(a3), "r"(b0), "r"(b1));
}
__device__ __forceinline__ void ldsm4(uint32_t* r, uint32_t addr) {
    asm volatile("ldmatrix.sync.aligned.m8n8.x4.shared.b16 {%0,%1,%2,%3}, [%4];"
        : "=r"(r[0]), "=r"(r[1]), "=r"(r[2]), "=r"(r[3]) : "r"(addr));
}
__device__ __forceinline__ uint32_t packbf(float lo, float hi) {
    __nv_bfloat162 p = __floats2bfloat162_rn(lo, hi);
    return *(uint32_t*)&p;
}
__device__ __forceinline__ float ex2f(float x) {
    float r; asm("ex2.approx.ftz.f32 %0, %1;" : "=f"(r) : "f"(x)); return r;
}
__device__ __forceinline__ float bflo(uint32_t u) { return __uint_as_float(u << 16); }
__device__ __forceinline__ float bfhi(uint32_t u) { return __uint_as_float(u & 0xffff0000u); }
__device__ __forceinline__ uint32_t f2tf32(float x) {
    uint32_t r; asm("cvt.rna.tf32.f32 %0, %1;" : "=r"(r) : "f"(x)); return r;
}

// ---------------- tf32 GEMM for proj_in: xf = W_in @ x, + xft bf16 ---------
// W [256,128] fp32; x [b][128][1024]; CTA 64m x 64n, 128 thr, K staged 2x64.
__global__ __launch_bounds__(128) void gemm_in(
    const float* __restrict__ W, const float* __restrict__ X)
{
    __shared__ uint32_t As[64 * 68];   // [m][k] tf32 bits
    __shared__ uint32_t Bs[64 * 68];   // [n][k] tf32 bits

    const int t = threadIdx.x;
    const int lane = t & 31, wid = t >> 5;
    const int gid = lane >> 2, kl = lane & 3, q2 = kl * 2;
    const int mblk = blockIdx.y * 64, nblk = blockIdx.x * 64, b = blockIdx.z;
    const int wm = wid * 16;

    float acc[8][4];
#pragma unroll
    for (int nt = 0; nt < 8; nt++)
#pragma unroll
        for (int j = 0; j < 4; j++) acc[nt][j] = 0.f;

    for (int ks = 0; ks < 128; ks += 64) {
        __syncthreads();
#pragma unroll
        for (int i = 0; i < 8; i++) {
            int idx = t + i * 128;
            int row = idx >> 4, c4 = (idx & 15) * 4;
            float4 av = *(const float4*)(W + (size_t)(mblk + row) * 128 + ks + c4);
            As[row * 68 + c4 + 0] = f2tf32(av.x);
            As[row * 68 + c4 + 1] = f2tf32(av.y);
            As[row * 68 + c4 + 2] = f2tf32(av.z);
            As[row * 68 + c4 + 3] = f2tf32(av.w);
            float4 bv = *(const float4*)(X + (size_t)b * 131072 +
                                         (size_t)(ks + row) * NTOK + nblk + c4);
            Bs[(c4 + 0) * 68 + row] = f2tf32(bv.x);
            Bs[(c4 + 1) * 68 + row] = f2tf32(bv.y);
            Bs[(c4 + 2) * 68 + row] = f2tf32(bv.z);
            Bs[(c4 + 3) * 68 + row] = f2tf32(bv.w);
        }
        __syncthreads();
#pragma unroll
        for (int kk = 0; kk < 64; kk += 8) {
            uint32_t a0 = As[(wm + gid) * 68 + kk + kl];
            uint32_t a1 = As[(wm + gid + 8) * 68 + kk + kl];
            uint32_t a2 = As[(wm + gid) * 68 + kk + kl + 4];
            uint32_t a3 = As[(wm + gid + 8) * 68 + kk + kl + 4];
#pragma unroll
            for (int nt = 0; nt < 8; nt++) {
                uint32_t b0 = Bs[(nt * 8 + gid) * 68 + kk + kl];
                uint32_t b1 = Bs[(nt * 8 + gid) * 68 + kk + kl + 4];
                mma1688tf(acc[nt], a0, a1, a2, a3, b0, b1);
            }
        }
    }

    float* xfb = g_xf + (size_t)b * C2D * NTOK;
    __nv_bfloat16* xtb = g_xft + (size_t)b * NTOK * C2D;
    const int r0 = mblk + wm + gid;
#pragma unroll
    for (int nt = 0; nt < 8; nt++) {
        int col = nblk + nt * 8 + q2;
        *(float2*)(xfb + (size_t)r0 * NTOK + col) =
            make_float2(acc[nt][0], acc[nt][1]);
        *(float2*)(xfb + (size_t)(r0 + 8) * NTOK + col) =
            make_float2(acc[nt][2], acc[nt][3]);
        xtb[(size_t)col * C2D + r0]           = __float2bfloat16(acc[nt][0]);
        xtb[(size_t)(col + 1) * C2D + r0]     = __float2bfloat16(acc[nt][1]);
        xtb[(size_t)col * C2D + r0 + 8]       = __float2bfloat16(acc[nt][2]);
        xtb[(size_t)(col + 1) * C2D + r0 + 8] = __float2bfloat16(acc[nt][3]);
    }
}

// ---------------- bf16 GEMM (ldmatrix): qkv-fused or fp32-out modes --------
#define GK 256
#define GLD 264
#define GEMMH_SMEM (2 * 64 * GLD * 2)
__global__ __launch_bounds__(128) void gemm_h(
    const __nv_bfloat16* __restrict__ Ah, const __nv_bfloat16* __restrict__ Xt,
    float* __restrict__ C, const float* __restrict__ add_src, int mode)
{
    extern __shared__ __nv_bfloat16 gs[];
    __nv_bfloat16* As = gs;
    __nv_bfloat16* Bs = gs + 64 * GLD;

    const int t = threadIdx.x;
    const int lane = t & 31, wid = t >> 5;
    const int gid = lane >> 2, q2 = (lane & 3) * 2;
    const int lrow = lane & 7, lmi = lane >> 3;
    const int mblk = blockIdx.y * 64, nblk = blockIdx.x * 64, b = blockIdx.z;
    const int wm = wid * 16;

    const __nv_bfloat16* Xb = Xt + ((size_t)b * NTOK + nblk) * GK;
#pragma unroll
    for (int i = 0; i < 16; i++) {
        int idx = t + i * 128;
        int row = idx >> 5, q = (idx & 31) * 8;
        *(uint4*)(As + row * GLD + q) = *(const uint4*)(Ah + (size_t)(mblk + row) * GK + q);
        *(uint4*)(Bs + row * GLD + q) = *(const uint4*)(Xb + (size_t)row * GK + q);
    }
    __syncthreads();

    const uint32_t as_b = smem_u32(As);
    const uint32_t bs_b = smem_u32(Bs);
    const uint32_t a_addr0 = as_b + 2 * ((wm + ((lmi & 1) << 3) + lrow) * GLD + ((lmi >> 1) << 3));
    const uint32_t b_row   = (uint32_t)(((lmi >> 1) << 3) + lrow) * GLD + ((lmi & 1) << 3);

    float acc[8][4];
#pragma unroll
    for (int nt = 0; nt < 8; nt++)
#pragma unroll
        for (int j = 0; j < 4; j++) acc[nt][j] = 0.f;

#pragma unroll
    for (int kt = 0; kt < GK / 16; kt++) {
        const int ka = kt * 16;
        uint32_t ar[4];
        ldsm4(ar, a_addr0 + 2 * ka);
#pragma unroll
        for (int np = 0; np < 4; np++) {
            uint32_t br[4];
            ldsm4(br, bs_b + 2 * (b_row + (np * 16) * GLD + ka));
            mma16816(acc[2 * np],     ar[0], ar[1], ar[2], ar[3], br[0], br[1]);
            mma16816(acc[2 * np + 1], ar[0], ar[1], ar[2], ar[3], br[2], br[3]);
        }
    }

    const int r0 = mblk + wm + gid;
    if (mode == 1) {
        // fused qkv epilogue: rows 0-255 q, 256-511 k, 512-767 v (bf16)
        const int sector = r0 >> 8;
        const int hh = (r0 >> 5) & 7, dd = r0 & 31;
        if (sector < 2) {
            __nv_bfloat16* base = (sector == 0 ? g_qh : g_kh) +
                (size_t)(b * NHEAD + hh) * NTOK * DHEAD;
#pragma unroll
            for (int nt = 0; nt < 8; nt++) {
                int n = nblk + nt * 8 + q2;
                base[(size_t)n * DHEAD + dd]           = __float2bfloat16(acc[nt][0]);
                base[(size_t)(n + 1) * DHEAD + dd]     = __float2bfloat16(acc[nt][1]);
                base[(size_t)n * DHEAD + dd + 8]       = __float2bfloat16(acc[nt][2]);
                base[(size_t)(n + 1) * DHEAD + dd + 8] = __float2bfloat16(acc[nt][3]);
            }
        } else {
            __nv_bfloat16* vb = g_vh + (size_t)(b * NHEAD + hh) * DHEAD * NTOK;
#pragma unroll
            for (int nt = 0; nt < 8; nt++) {
                int n = nblk + nt * 8 + q2;
                *(uint32_t*)(vb + (size_t)dd * NTOK + n)       = packbf(acc[nt][0], acc[nt][1]);
                *(uint32_t*)(vb + (size_t)(dd + 8) * NTOK + n) = packbf(acc[nt][2], acc[nt][3]);
            }
        }
    } else {
        float* Cb = C + (size_t)b * C2D * NTOK;
        const float* ab = add_src + (size_t)b * C2D * NTOK;
#pragma unroll
        for (int nt = 0; nt < 8; nt++) {
            int col = nblk + nt * 8 + q2;
            float2 a0 = *(const float2*)(ab + (size_t)r0 * NTOK + col);
            float2 a1 = *(const float2*)(ab + (size_t)(r0 + 8) * NTOK + col);
            *(float2*)(Cb + (size_t)r0 * NTOK + col) =
                make_float2(acc[nt][0] + a0.x, acc[nt][1] + a0.y);
            *(float2*)(Cb + (size_t)(r0 + 8) * NTOK + col) =
                make_float2(acc[nt][2] + a1.x, acc[nt][3] + a1.y);
        }
    }
}

// ---------------- attention (mma.sync + ldmatrix) --------------------------
#define ROWT 64
#define KS_LD 40
#define VT_LD 136

__global__ void __launch_bounds__(128, 4) attn_kernel()
{
    __shared__ __align__(16) __nv_bfloat16 Ks[128 * KS_LD];
    __shared__ __align__(16) __nv_bfloat16 Vt[DHEAD * VT_LD];
    __shared__ float pm_s [KCL * 128];
    __shared__ float pme_s[KCL * 128];

    const int t    = threadIdx.x;
    const int wid  = t >> 5;
    const int lane = t & 31;
    const int gid  = lane >> 2;
    const int q2   = (lane & 3) * 2;
    const int lrow = lane & 7, lmi = lane >> 3;

    const int n0 = blockIdx.x * ROWT;
    const int h  = blockIdx.y;
    const int b  = blockIdx.z;

    const __nv_bfloat16* qh = g_qh + (size_t)(b * NHEAD + h) * NTOK * DHEAD;
    const __nv_bfloat16* kh = g_kh + (size_t)(b * NHEAD + h) * NTOK * DHEAD;
    const __nv_bfloat16* vh = g_vh + (size_t)(b * NHEAD + h) * DHEAD * NTOK;
    const float* pbase  = g_prob  + (size_t)b * KCL * NTOK;
    const float* pebase = g_probe + (size_t)b * KCL * NTOK;

    const int n_g = n0 + wid * 16 + gid;

    uint32_t qa[2][4];
#pragma unroll
    for (int kt = 0; kt < 2; kt++) {
        int d0 = kt * 16 + q2;
        qa[kt][0] = *(const uint32_t*)(qh + (size_t)n_g * DHEAD + d0);
        qa[kt][1] = *(const uint32_t*)(qh + (size_t)(n_g + 8) * DHEAD + d0);
        qa[kt][2] = *(const uint32_t*)(qh + (size_t)n_g * DHEAD + d0 + 8);
        qa[kt][3] = *(const uint32_t*)(qh + (size_t)(n_g + 8) * DHEAD + d0 + 8);
    }

    float pn0[KCL], pn1[KCL];
#pragma unroll
    for (int i = 0; i < KCL; i++) {
        pn0[i] = pbase[i * NTOK + n_g];
        pn1[i] = pbase[i * NTOK + n_g + 8];
    }

    float oacc[KCL][4][4];
    float lacc[KCL][2];
#pragma unroll
    for (int i = 0; i < KCL; i++) {
        lacc[i][0] = lacc[i][1] = 0.f;
#pragma unroll
        for (int dt = 0; dt < 4; dt++)
#pragma unroll
            for (int j = 0; j < 4; j++) oacc[i][dt][j] = 0.f;
    }

    const uint32_t ks_b = smem_u32(Ks);
    const uint32_t vt_b = smem_u32(Vt);
    // K ldsm: per nt, 4 matrices at k-cols {0,8,16,24}, rows c0+nt*8+lrow
    const uint32_t k_off = (uint32_t)lrow * KS_LD + lmi * 8;
    // V ldsm: per dt-pair dp, matrices rows (dp*2 + lmi>>1)*8+lrow, cols +{0,8}
    const uint32_t v_off = (uint32_t)(((lmi >> 1) << 3) + lrow) * VT_LD + ((lmi & 1) << 3);

    for (int mt = 0; mt < NTOK; mt += 128) {
        __syncthreads();
#pragma unroll
        for (int i = 0; i < 4; i++) {
            int idx = t + i * 128;
            int row = idx >> 2, q = (idx & 3) * 8;
            *(uint4*)(Ks + row * KS_LD + q) =
                *(const uint4*)(kh + (size_t)(mt + row) * DHEAD + q);
        }
#pragma unroll
        for (int i = 0; i < 4; i++) {
            int idx = t + i * 128;
            int d = idx >> 4, q = (idx & 15) * 8;
            *(uint4*)(Vt + d * VT_LD + q) =
                *(const uint4*)(vh + (size_t)d * NTOK + mt + q);
        }
#pragma unroll
        for (int i = 0; i < 3; i++) {
            int idx = t + i * 128;
            int cl = idx >> 7, m = idx & 127;
            pm_s [cl * 128 + m] = pbase [(size_t)cl * NTOK + mt + m];
            pme_s[cl * 128 + m] = pebase[(size_t)cl * NTOK + mt + m];
        }
        __syncthreads();

#pragma unroll
        for (int chunk = 0; chunk < 4; chunk++) {
            const int c0 = chunk * 32;
            // S = Q K^T for 32 keys
            float sacc[4][4];
#pragma unroll
            for (int nt = 0; nt < 4; nt++) {
                sacc[nt][0] = sacc[nt][1] = sacc[nt][2] = sacc[nt][3] = 0.f;
                uint32_t br[4];
                ldsm4(br, ks_b + 2 * ((uint32_t)(c0 + nt * 8) * KS_LD + k_off));
                mma16816(sacc[nt], qa[0][0], qa[0][1], qa[0][2], qa[0][3], br[0], br[1]);
                mma16816(sacc[nt], qa[1][0], qa[1][1], qa[1][2], qa[1][3], br[2], br[3]);
            }
            // hoisted V fragments (shared across clusters)
            uint32_t vr[2][2][4];
#pragma unroll
            for (int s = 0; s < 2; s++)
#pragma unroll
                for (int dp = 0; dp < 2; dp++)
                    ldsm4(vr[s][dp], vt_b + 2 * ((uint32_t)(dp * 16) * VT_LD + v_off
                                               + (uint32_t)(c0 + 16 * s)));

#pragma unroll
            for (int i = 0; i < KCL; i++) {
                const float cr0 = pn0[i], cr1 = pn1[i];
                const float* pmp  = pm_s  + i * 128 + c0;
                const float* pmep = pme_s + i * 128 + c0;
                float l0 = 0.f, l1 = 0.f;
#pragma unroll
                for (int s = 0; s < 2; s++) {
                    const float* pc  = pmp  + 16 * s;
                    const float* pce = pmep + 16 * s;
                    float pm00 = pc[q2],      pm01 = pc[q2 + 1];
                    float pm10 = pc[q2 + 8],  pm11 = pc[q2 + 9];
                    float pe00 = pce[q2],     pe01 = pce[q2 + 1];
                    float pe10 = pce[q2 + 8], pe11 = pce[q2 + 9];
                    const int j0 = 2 * s, j1 = 2 * s + 1;
                    float e00 = ex2f(sacc[j0][0] * cr0 * pe00);
                    float e01 = ex2f(sacc[j0][1] * cr0 * pe01);
                    float e02 = ex2f(sacc[j0][2] * cr1 * pe00);
                    float e03 = ex2f(sacc[j0][3] * cr1 * pe01);
                    float e10 = ex2f(sacc[j1][0] * cr0 * pe10);
                    float e11 = ex2f(sacc[j1][1] * cr0 * pe11);
                    float e12 = ex2f(sacc[j1][2] * cr1 * pe10);
                    float e13 = ex2f(sacc[j1][3] * cr1 * pe11);
                    l0 += e00 + e01 + e10 + e11;
                    l1 += e02 + e03 + e12 + e13;
                    uint32_t ra0 = packbf(e00 * pm00, e01 * pm01);
                    uint32_t ra1 = packbf(e02 * pm00, e03 * pm01);
                    uint32_t ra2 = packbf(e10 * pm10, e11 * pm11);
                    uint32_t ra3 = packbf(e12 * pm10, e13 * pm11);
#pragma unroll
                    for (int dt = 0; dt < 4; dt++)
                        mma16816(oacc[i][dt], ra0, ra1, ra2, ra3,
                                 vr[s][dt >> 1][(dt & 1) * 2],
                                 vr[s][dt >> 1][(dt & 1) * 2 + 1]);
                }
                lacc[i][0] += l0;
                lacc[i][1] += l1;
            }
        }
    }

    float inv0[KCL], inv1[KCL];
#pragma unroll
    for (int i = 0; i < KCL; i++) {
        float l0 = lacc[i][0], l1 = lacc[i][1];
        l0 += __shfl_xor_sync(0xffffffffu, l0, 1);
        l0 += __shfl_xor_sync(0xffffffffu, l0, 2);
        l1 += __shfl_xor_sync(0xffffffffu, l1, 1);
        l1 += __shfl_xor_sync(0xffffffffu, l1, 2);
        inv0[i] = __fdividef(1.f, 3.f * l0);
        inv1[i] = __fdividef(1.f, 3.f * l1);
    }

    __nv_bfloat16* ob0 = g_attt + ((size_t)b * NTOK + n_g)     * C2D + h * DHEAD;
    __nv_bfloat16* ob1 = g_attt + ((size_t)b * NTOK + n_g + 8) * C2D + h * DHEAD;
#pragma unroll
    for (int dt = 0; dt < 4; dt++) {
        int d0 = dt * 8 + q2;
        float o00 = 0.f, o01 = 0.f, o10 = 0.f, o11 = 0.f;
#pragma unroll
        for (int i = 0; i < KCL; i++) {
            o00 += oacc[i][dt][0] * inv0[i];
            o01 += oacc[i][dt][1] * inv0[i];
            o10 += oacc[i][dt][2] * inv1[i];
            o11 += oacc[i][dt][3] * inv1[i];
        }
        *(uint32_t*)(ob0 + d0) = packbf(o00, o01);
        *(uint32_t*)(ob1 + d0) = packbf(o10, o11);
    }
}

// ---------------- converts -------------------------------------------------
__global__ __launch_bounds__(256) void conv_w(
    const float* __restrict__ Wq, const float* __restrict__ Wp)
{
    int idx = blockIdx.x * 256 + threadIdx.x;
    if (idx < 3 * C2D * C2D) g_wqh[idx] = __float2bfloat16(Wq[idx]);
    else {
        int j = idx - 3 * C2D * C2D;
        if (j < C2D * C2D) g_wph[j] = __float2bfloat16(Wp[j]);
    }
}

// ---------------- cluster probs (bf16 xft, 4 threads/token) ----------------
__global__ __launch_bounds__(256) void prob_kernel(
    const float* __restrict__ Wc, const float* __restrict__ bc)
{
    __shared__ float W[KCL * C2D];
    __shared__ float bias[KCL];
    const int t = threadIdx.x;
    for (int i = t; i < KCL * C2D; i += 256) W[i] = Wc[i];
    if (t < KCL) bias[t] = bc[t];
    __syncthreads();

    const int gidx = blockIdx.x * 256 + t;
    const int tok = gidx >> 2;
    const int p   = t & 3;
    const int b = tok >> 10, n = tok & 1023;

    const __nv_bfloat16* xp = g_xft + ((size_t)(b * NTOK + n)) * C2D + p * 64;
    const float* W0 = W + p * 64;
    float l0 = 0.f, l1 = 0.f, l2 = 0.f;
#pragma unroll
    for (int j = 0; j < 8; j++) {
        uint4 v = *(const uint4*)(xp + j * 8);
        const float* w = W0 + j * 8;
        float x0 = bflo(v.x), x1 = bfhi(v.x);
        float x2 = bflo(v.y), x3 = bfhi(v.y);
        float x4 = bflo(v.z), x5 = bfhi(v.z);
        float x6 = bflo(v.w), x7 = bfhi(v.w);
        l0 = fmaf(w[0], x0, l0); l0 = fmaf(w[1], x1, l0);
        l0 = fmaf(w[2], x2, l0); l0 = fmaf(w[3], x3, l0);
        l0 = fmaf(w[4], x4, l0); l0 = fmaf(w[5], x5, l0);
        l0 = fmaf(w[6], x6, l0); l0 = fmaf(w[7], x7, l0);
        l1 = fmaf(w[C2D + 0], x0, l1); l1 = fmaf(w[C2D + 1], x1, l1);
        l1 = fmaf(w[C2D + 2], x2, l1); l1 = fmaf(w[C2D + 3], x3, l1);
        l1 = fmaf(w[C2D + 4], x4, l1); l1 = fmaf(w[C2D + 5], x5, l1);
        l1 = fmaf(w[C2D + 6], x6, l1); l1 = fmaf(w[C2D + 7], x7, l1);
        l2 = fmaf(w[2 * C2D + 0], x0, l2); l2 = fmaf(w[2 * C2D + 1], x1, l2);
        l2 = fmaf(w[2 * C2D + 2], x2, l2); l2 = fmaf(w[2 * C2D + 3], x3, l2);
        l2 = fmaf(w[2 * C2D + 4], x4, l2); l2 = fmaf(w[2 * C2D + 5], x5, l2);
        l2 = fmaf(w[2 * C2D + 6], x6, l2); l2 = fmaf(w[2 * C2D + 7], x7, l2);
    }
    l0 += __shfl_xor_sync(0xffffffffu, l0, 1);
    l0 += __shfl_xor_sync(0xffffffffu, l0, 2);
    l1 += __shfl_xor_sync(0xffffffffu, l1, 1);
    l1 += __shfl_xor_sync(0xffffffffu, l1, 2);
    l2 += __shfl_xor_sync(0xffffffffu, l2, 1);
    l2 += __shfl_xor_sync(0xffffffffu, l2, 2);

    if (p == 0) {
        l0 += bias[0]; l1 += bias[1]; l2 += bias[2];
        float mx = fmaxf(l0, fmaxf(l1, l2));
        float e0 = __expf(l0 - mx), e1 = __expf(l1 - mx), e2 = __expf(l2 - mx);
        float inv = 1.f / (e0 + e1 + e2);
        float p0 = e0 * inv, p1 = e1 * inv, p2 = e2 * inv;
        float* pb  = g_prob  + (size_t)b * KCL * NTOK + n;
        float* peb = g_probe + (size_t)b * KCL * NTOK + n;
        pb[0]        = p0;  peb[0]        = p0 * EXPSC;
        pb[NTOK]     = p1;  peb[NTOK]     = p1 * EXPSC;
        pb[2 * NTOK] = p2;  peb[2 * NTOK] = p2 * EXPSC;
    }
}

// ---------------- launch ---------------------------------------------------
extern "C" void kernel_launch(void* const* d_in, const int* in_sizes, int n_in,
                              void* d_out, int out_size)
{
    const float* x      = (const float*)d_in[0];
    const float* W_in   = (const float*)d_in[1];
    const float* Wc     = (const float*)d_in[2];
    const float* bc     = (const float*)d_in[3];
    const float* W_qkv  = (const float*)d_in[4];
    const float* W_proj = (const float*)d_in[5];
    float* out = (float*)d_out;

    float* xf;
    __nv_bfloat16 *wqh, *wph, *xft, *attt;
    cudaGetSymbolAddress((void**)&xf,   g_xf);
    cudaGetSymbolAddress((void**)&wqh,  g_wqh);
    cudaGetSymbolAddress((void**)&wph,  g_wph);
    cudaGetSymbolAddress((void**)&xft,  g_xft);
    cudaGetSymbolAddress((void**)&attt, g_attt);

    cudaFuncSetAttribute(gemm_h,
        cudaFuncAttributeMaxDynamicSharedMemorySize, GEMMH_SMEM);

    // 1) xf = W_in @ x (tf32 tensor) + fused bf16 transpose to xft
    gemm_in<<<dim3(16, 4, BDIM), 128>>>(W_in, x);
    // 2) weight conversions + cluster probs (from xft)
    conv_w<<<1024, 256>>>(W_qkv, W_proj);
    prob_kernel<<<(BDIM * NTOK * 4) / 256, 256>>>(Wc, bc);
    // 3) qkv GEMM (bf16 + ldmatrix), epilogue writes q/k/v bf16 layouts
    gemm_h<<<dim3(16, 12, BDIM), 128, GEMMH_SMEM>>>(wqh, xft, nullptr, nullptr, 1);
    // 4) clustered attention
    attn_kernel<<<dim3(NTOK / ROWT, NHEAD, BDIM), 128>>>();
    // 5) out = W_proj @ att + xf (bf16 + ldmatrix, fp32 identity add)
    gemm_h<<<dim3(16, 4, BDIM), 128, GEMMH_SMEM>>>(wph, attt, out, xf, 0);
}

// round 13
// speedup vs baseline: 7.5773x; 1.0616x over previous
#include <cuda_runtime.h>
#include <cuda_bf16.h>
#include <math.h>
#include <stdint.h>

#define BDIM  8
#define C2D   256
#define NTOK  1024
#define NHEAD 8
#define DHEAD 32
#define KCL   3
#define QKSCALE 0.17677669529663687f
#define EXPSC  (0.17677669529663687f * 1.4426950408889634f)

// ---------------- scratch ----------------
__device__ float g_xf  [BDIM * C2D * NTOK];
__device__ float g_prob[BDIM * KCL * NTOK];
__device__ float g_probe[BDIM * KCL * NTOK];
__device__ __nv_bfloat16 g_wqh [3 * C2D * C2D];
__device__ __nv_bfloat16 g_wph [C2D * C2D];
__device__ __nv_bfloat16 g_xft [BDIM * NTOK * C2D];
__device__ __nv_bfloat16 g_qh  [BDIM * NHEAD * NTOK * DHEAD];
__device__ __nv_bfloat16 g_kh  [BDIM * NHEAD * NTOK * DHEAD];
__device__ __nv_bfloat16 g_vh  [BDIM * NHEAD * DHEAD * NTOK];
__device__ __nv_bfloat16 g_attt[BDIM * NTOK * C2D];

// ---------------- helpers ----------------
__device__ __forceinline__ uint32_t smem_u32(const void* p) {
    uint32_t a;
    asm("{ .reg .u64 t; cvta.to.shared.u64 t, %1; cvt.u32.u64 %0, t; }" : "=r"(a) : "l"(p));
    return a;
}
__device__ __forceinline__ void mma16816(float* d,
    uint32_t a0, uint32_t a1, uint32_t a2, uint32_t a3,
    uint32_t b0, uint32_t b1)
{
    asm volatile(
        "mma.sync.aligned.m16n8k16.row.col.f32.bf16.bf16.f32 "
        "{%0,%1,%2,%3}, {%4,%5,%6,%7}, {%8,%9}, {%0,%1,%2,%3};"
        : "+f"(d[0]), "+f"(d[1]), "+f"(d[2]), "+f"(d[3])
        : "r"(a0), "r"(a1), "r"(a2), "r"(a3), "r"(b0), "r"(b1));
}
__device__ __forceinline__ void mma1688tf(float* d,
    uint32_t a0, uint32_t a1, uint32_t a2, uint32_t a3,
    uint32_t b0, uint32_t b1)
{
    asm volatile(
        "mma.sync.aligned.m16n8k8.row.col.f32.tf32.tf32.f32 "
        "{%0,%1,%2,%3}, {%4,%5,%6,%7}, {%8,%9}, {%0,%1,%2,%3};"
        : "+f"(d[0]), "+f"(d[1]), "+f"(d[2]), "+f"(d[3])
        : "r"(a0), "r"(a1), "r"(a2), "r"(a3), "r"(b0), "r"(b1));
}
__device__ __forceinline__ void ldsm4(uint32_t* r, uint32_t addr) {
    asm volatile("ldmatrix.sync.aligned.m8n8.x4.shared.b16 {%0,%1,%2,%3}, [%4];"
        : "=r"(r[0]), "=r"(r[1]), "=r"(r[2]), "=r"(r[3]) : "r"(addr));
}
__device__ __forceinline__ uint32_t packbf(float lo, float hi) {
    __nv_bfloat162 p = __floats2bfloat162_rn(lo, hi);
    return *(uint32_t*)&p;
}
__device__ __forceinline__ float ex2f(float x) {
    float r; asm("ex2.approx.ftz.f32 %0, %1;" : "=f"(r) : "f"(x)); return r;
}
__device__ __forceinline__ float bflo(uint32_t u) { return __uint_as_float(u << 16); }
__device__ __forceinline__ float bfhi(uint32_t u) { return __uint_as_float(u & 0xffff0000u); }
__device__ __forceinline__ uint32_t f2tf32(float x) {
    uint32_t r; asm("cvt.rna.tf32.f32 %0, %1;" : "=r"(r) : "f"(x)); return r;
}
__device__ __forceinline__ void cpa16(uint32_t s, const void* g) {
    asm volatile("{ .reg .u64 gg; cvta.to.global.u64 gg, %1; "
                 "cp.async.cg.shared.global [%0], [gg], 16; }" :: "r"(s), "l"(g));
}
__device__ __forceinline__ void cpa4(uint32_t s, const void* g) {
    asm volatile("{ .reg .u64 gg; cvta.to.global.u64 gg, %1; "
                 "cp.async.ca.shared.global [%0], [gg], 4; }" :: "r"(s), "l"(g));
}
#define CP_COMMIT() asm volatile("cp.async.commit_group;" ::: "memory")
#define CP_WAIT1()  asm volatile("cp.async.wait_group 1;" ::: "memory")
#define CP_WAIT0()  asm volatile("cp.async.wait_group 0;" ::: "memory")

// ---------------- tf32 GEMM for proj_in: xf = W_in @ x, + xft bf16 ---------
__global__ __launch_bounds__(128) void gemm_in(
    const float* __restrict__ W, const float* __restrict__ X)
{
    __shared__ uint32_t As[64 * 68];
    __shared__ uint32_t Bs[64 * 68];

    const int t = threadIdx.x;
    const int lane = t & 31, wid = t >> 5;
    const int gid = lane >> 2, kl = lane & 3, q2 = kl * 2;
    const int mblk = blockIdx.y * 64, nblk = blockIdx.x * 64, b = blockIdx.z;
    const int wm = wid * 16;

    float acc[8][4];
#pragma unroll
    for (int nt = 0; nt < 8; nt++)
#pragma unroll
        for (int j = 0; j < 4; j++) acc[nt][j] = 0.f;

    for (int ks = 0; ks < 128; ks += 64) {
        __syncthreads();
#pragma unroll
        for (int i = 0; i < 8; i++) {
            int idx = t + i * 128;
            int row = idx >> 4, c4 = (idx & 15) * 4;
            float4 av = *(const float4*)(W + (size_t)(mblk + row) * 128 + ks + c4);
            As[row * 68 + c4 + 0] = f2tf32(av.x);
            As[row * 68 + c4 + 1] = f2tf32(av.y);
            As[row * 68 + c4 + 2] = f2tf32(av.z);
            As[row * 68 + c4 + 3] = f2tf32(av.w);
            float4 bv = *(const float4*)(X + (size_t)b * 131072 +
                                         (size_t)(ks + row) * NTOK + nblk + c4);
            Bs[(c4 + 0) * 68 + row] = f2tf32(bv.x);
            Bs[(c4 + 1) * 68 + row] = f2tf32(bv.y);
            Bs[(c4 + 2) * 68 + row] = f2tf32(bv.z);
            Bs[(c4 + 3) * 68 + row] = f2tf32(bv.w);
        }
        __syncthreads();
#pragma unroll
        for (int kk = 0; kk < 64; kk += 8) {
            uint32_t a0 = As[(wm + gid) * 68 + kk + kl];
            uint32_t a1 = As[(wm + gid + 8) * 68 + kk + kl];
            uint32_t a2 = As[(wm + gid) * 68 + kk + kl + 4];
            uint32_t a3 = As[(wm + gid + 8) * 68 + kk + kl + 4];
#pragma unroll
            for (int nt = 0; nt < 8; nt++) {
                uint32_t b0 = Bs[(nt * 8 + gid) * 68 + kk + kl];
                uint32_t b1 = Bs[(nt * 8 + gid) * 68 + kk + kl + 4];
                mma1688tf(acc[nt], a0, a1, a2, a3, b0, b1);
            }
        }
    }

    float* xfb = g_xf + (size_t)b * C2D * NTOK;
    __nv_bfloat16* xtb = g_xft + (size_t)b * NTOK * C2D;
    const int r0 = mblk + wm + gid;
#pragma unroll
    for (int nt = 0; nt < 8; nt++) {
        int col = nblk + nt * 8 + q2;
        *(float2*)(xfb + (size_t)r0 * NTOK + col) =
            make_float2(acc[nt][0], acc[nt][1]);
        *(float2*)(xfb + (size_t)(r0 + 8) * NTOK + col) =
            make_float2(acc[nt][2], acc[nt][3]);
        xtb[(size_t)col * C2D + r0]           = __float2bfloat16(acc[nt][0]);
        xtb[(size_t)(col + 1) * C2D + r0]     = __float2bfloat16(acc[nt][1]);
        xtb[(size_t)col * C2D + r0 + 8]       = __float2bfloat16(acc[nt][2]);
        xtb[(size_t)(col + 1) * C2D + r0 + 8] = __float2bfloat16(acc[nt][3]);
    }
}

// ---------------- bf16 GEMM (ldmatrix, K-chunked for occupancy) ------------
#define GK   256
#define GCH  128
#define GLD2 136
__global__ __launch_bounds__(128) void gemm_h(
    const __nv_bfloat16* __restrict__ Ah, const __nv_bfloat16* __restrict__ Xt,
    float* __restrict__ C, const float* __restrict__ add_src, int mode)
{
    __shared__ __align__(16) __nv_bfloat16 As[64 * GLD2];
    __shared__ __align__(16) __nv_bfloat16 Bs[64 * GLD2];

    const int t = threadIdx.x;
    const int lane = t & 31, wid = t >> 5;
    const int gid = lane >> 2, q2 = (lane & 3) * 2;
    const int lrow = lane & 7, lmi = lane >> 3;
    const int mblk = blockIdx.y * 64, nblk = blockIdx.x * 64, b = blockIdx.z;
    const int wm = wid * 16;

    const __nv_bfloat16* Xb = Xt + ((size_t)b * NTOK + nblk) * GK;
    const uint32_t as_b = smem_u32(As);
    const uint32_t bs_b = smem_u32(Bs);
    const uint32_t a_addr0 = as_b + 2 * ((wm + ((lmi & 1) << 3) + lrow) * GLD2 + ((lmi >> 1) << 3));
    const uint32_t b_row   = (uint32_t)(((lmi >> 1) << 3) + lrow) * GLD2 + ((lmi & 1) << 3);

    float acc[8][4];
#pragma unroll
    for (int nt = 0; nt < 8; nt++)
#pragma unroll
        for (int j = 0; j < 4; j++) acc[nt][j] = 0.f;

#pragma unroll
    for (int kc = 0; kc < 2; kc++) {
        __syncthreads();
        const __nv_bfloat16* Ab = Ah + (size_t)mblk * GK + kc * GCH;
        const __nv_bfloat16* Bb = Xb + kc * GCH;
#pragma unroll
        for (int i = 0; i < 8; i++) {
            int idx = t + i * 128;
            int row = idx >> 4, q = (idx & 15) * 8;
            *(uint4*)(As + row * GLD2 + q) = *(const uint4*)(Ab + (size_t)row * GK + q);
            *(uint4*)(Bs + row * GLD2 + q) = *(const uint4*)(Bb + (size_t)row * GK + q);
        }
        __syncthreads();
#pragma unroll
        for (int kt = 0; kt < GCH / 16; kt++) {
            const int ka = kt * 16;
            uint32_t ar[4];
            ldsm4(ar, a_addr0 + 2 * ka);
#pragma unroll
            for (int np = 0; np < 4; np++) {
                uint32_t br[4];
                ldsm4(br, bs_b + 2 * (b_row + (np * 16) * GLD2 + ka));
                mma16816(acc[2 * np],     ar[0], ar[1], ar[2], ar[3], br[0], br[1]);
                mma16816(acc[2 * np + 1], ar[0], ar[1], ar[2], ar[3], br[2], br[3]);
            }
        }
    }

    const int r0 = mblk + wm + gid;
    if (mode == 1) {
        const int sector = r0 >> 8;
        const int hh = (r0 >> 5) & 7, dd = r0 & 31;
        if (sector < 2) {
            __nv_bfloat16* base = (sector == 0 ? g_qh : g_kh) +
                (size_t)(b * NHEAD + hh) * NTOK * DHEAD;
#pragma unroll
            for (int nt = 0; nt < 8; nt++) {
                int n = nblk + nt * 8 + q2;
                base[(size_t)n * DHEAD + dd]           = __float2bfloat16(acc[nt][0]);
                base[(size_t)(n + 1) * DHEAD + dd]     = __float2bfloat16(acc[nt][1]);
                base[(size_t)n * DHEAD + dd + 8]       = __float2bfloat16(acc[nt][2]);
                base[(size_t)(n + 1) * DHEAD + dd + 8] = __float2bfloat16(acc[nt][3]);
            }
        } else {
            __nv_bfloat16* vb = g_vh + (size_t)(b * NHEAD + hh) * DHEAD * NTOK;
#pragma unroll
            for (int nt = 0; nt < 8; nt++) {
                int n = nblk + nt * 8 + q2;
                *(uint32_t*)(vb + (size_t)dd * NTOK + n)       = packbf(acc[nt][0], acc[nt][1]);
                *(uint32_t*)(vb + (size_t)(dd + 8) * NTOK + n) = packbf(acc[nt][2], acc[nt][3]);
            }
        }
    } else {
        float* Cb = C + (size_t)b * C2D * NTOK;
        const float* ab = add_src + (size_t)b * C2D * NTOK;
#pragma unroll
        for (int nt = 0; nt < 8; nt++) {
            int col = nblk + nt * 8 + q2;
            float2 a0 = *(const float2*)(ab + (size_t)r0 * NTOK + col);
            float2 a1 = *(const float2*)(ab + (size_t)(r0 + 8) * NTOK + col);
            *(float2*)(Cb + (size_t)r0 * NTOK + col) =
                make_float2(acc[nt][0] + a0.x, acc[nt][1] + a0.y);
            *(float2*)(Cb + (size_t)(r0 + 8) * NTOK + col) =
                make_float2(acc[nt][2] + a1.x, acc[nt][3] + a1.y);
        }
    }
}

// ---------------- attention (mma.sync + ldmatrix + cp.async pipeline) ------
#define ROWT 64
#define KS_LD 40
#define VT_LD 136
#define KS_BYTES (128 * KS_LD * 2)
#define VT_BYTES (DHEAD * VT_LD * 2)
#define PM_BYTES (KCL * 128 * 4)

__global__ void __launch_bounds__(128, 4) attn_kernel()
{
    __shared__ __align__(16) __nv_bfloat16 Ks[2][128 * KS_LD];
    __shared__ __align__(16) __nv_bfloat16 Vt[2][DHEAD * VT_LD];
    __shared__ float pm_s [2][KCL * 128];
    __shared__ float pme_s[2][KCL * 128];

    const int t    = threadIdx.x;
    const int wid  = t >> 5;
    const int lane = t & 31;
    const int gid  = lane >> 2;
    const int q2   = (lane & 3) * 2;
    const int lrow = lane & 7, lmi = lane >> 3;

    const int n0 = blockIdx.x * ROWT;
    const int h  = blockIdx.y;
    const int b  = blockIdx.z;

    const __nv_bfloat16* qh = g_qh + (size_t)(b * NHEAD + h) * NTOK * DHEAD;
    const __nv_bfloat16* kh = g_kh + (size_t)(b * NHEAD + h) * NTOK * DHEAD;
    const __nv_bfloat16* vh = g_vh + (size_t)(b * NHEAD + h) * DHEAD * NTOK;
    const float* pbase  = g_prob  + (size_t)b * KCL * NTOK;
    const float* pebase = g_probe + (size_t)b * KCL * NTOK;

    const int n_g = n0 + wid * 16 + gid;

    const uint32_t ks_u  = smem_u32(Ks);
    const uint32_t vt_u  = smem_u32(Vt);
    const uint32_t pm_u  = smem_u32(pm_s);
    const uint32_t pme_u = smem_u32(pme_s);

    // staging: issue cp.async for tile at mt into buffer bufi
    const int st_krow = t >> 2, st_kq = (t & 3) * 8;      // K: 4 iters
    const int st_vd   = t >> 4, st_vq = (t & 15) * 8;     // V: 4 iters
    auto stage = [&](int mt, int bufi) {
        uint32_t kb = ks_u + bufi * KS_BYTES;
        uint32_t vb = vt_u + bufi * VT_BYTES;
#pragma unroll
        for (int i = 0; i < 4; i++) {
            int row = st_krow + i * 32;
            cpa16(kb + (uint32_t)(row * KS_LD + st_kq) * 2,
                  kh + (size_t)(mt + row) * DHEAD + st_kq);
        }
#pragma unroll
        for (int i = 0; i < 4; i++) {
            int d = st_vd + i * 8;
            cpa16(vb + (uint32_t)(d * VT_LD + st_vq) * 2,
                  vh + (size_t)d * NTOK + mt + st_vq);
        }
#pragma unroll
        for (int i = 0; i < 3; i++) {
            int idx = t + i * 128;
            int cl = idx >> 7, m = idx & 127;
            cpa4(pm_u  + (uint32_t)(bufi * KCL * 128 + cl * 128 + m) * 4,
                 pbase  + (size_t)cl * NTOK + mt + m);
            cpa4(pme_u + (uint32_t)(bufi * KCL * 128 + cl * 128 + m) * 4,
                 pebase + (size_t)cl * NTOK + mt + m);
        }
    };

    uint32_t qa[2][4];
#pragma unroll
    for (int kt = 0; kt < 2; kt++) {
        int d0 = kt * 16 + q2;
        qa[kt][0] = *(const uint32_t*)(qh + (size_t)n_g * DHEAD + d0);
        qa[kt][1] = *(const uint32_t*)(qh + (size_t)(n_g + 8) * DHEAD + d0);
        qa[kt][2] = *(const uint32_t*)(qh + (size_t)n_g * DHEAD + d0 + 8);
        qa[kt][3] = *(const uint32_t*)(qh + (size_t)(n_g + 8) * DHEAD + d0 + 8);
    }

    float pn0[KCL], pn1[KCL];
#pragma unroll
    for (int i = 0; i < KCL; i++) {
        pn0[i] = pbase[i * NTOK + n_g];
        pn1[i] = pbase[i * NTOK + n_g + 8];
    }

    float oacc[KCL][4][4];
    float lacc[KCL][2];
#pragma unroll
    for (int i = 0; i < KCL; i++) {
        lacc[i][0] = lacc[i][1] = 0.f;
#pragma unroll
        for (int dt = 0; dt < 4; dt++)
#pragma unroll
            for (int j = 0; j < 4; j++) oacc[i][dt][j] = 0.f;
    }

    const uint32_t k_off = (uint32_t)lrow * KS_LD + lmi * 8;
    const uint32_t v_off = (uint32_t)(((lmi >> 1) << 3) + lrow) * VT_LD + ((lmi & 1) << 3);

    stage(0, 0);
    CP_COMMIT();

    int buf = 0;
    for (int it = 0; it < 8; it++) {
        if (it) __syncthreads();              // nbuf readers done before reuse
        if (it < 7) { stage((it + 1) * 128, buf ^ 1); CP_COMMIT(); CP_WAIT1(); }
        else CP_WAIT0();
        __syncthreads();

        const uint32_t ks_b = ks_u + buf * KS_BYTES;
        const uint32_t vt_b = vt_u + buf * VT_BYTES;
        const float* pmb  = pm_s [buf];
        const float* pmeb = pme_s[buf];

#pragma unroll
        for (int chunk = 0; chunk < 4; chunk++) {
            const int c0 = chunk * 32;
            float sacc[4][4];
#pragma unroll
            for (int nt = 0; nt < 4; nt++) {
                sacc[nt][0] = sacc[nt][1] = sacc[nt][2] = sacc[nt][3] = 0.f;
                uint32_t br[4];
                ldsm4(br, ks_b + 2 * ((uint32_t)(c0 + nt * 8) * KS_LD + k_off));
                mma16816(sacc[nt], qa[0][0], qa[0][1], qa[0][2], qa[0][3], br[0], br[1]);
                mma16816(sacc[nt], qa[1][0], qa[1][1], qa[1][2], qa[1][3], br[2], br[3]);
            }
            uint32_t vr[2][2][4];
#pragma unroll
            for (int s = 0; s < 2; s++)
#pragma unroll
                for (int dp = 0; dp < 2; dp++)
                    ldsm4(vr[s][dp], vt_b + 2 * ((uint32_t)(dp * 16) * VT_LD + v_off
                                               + (uint32_t)(c0 + 16 * s)));

#pragma unroll
            for (int i = 0; i < KCL; i++) {
                const float cr0 = pn0[i], cr1 = pn1[i];
                const float* pmp  = pmb  + i * 128 + c0;
                const float* pmep = pmeb + i * 128 + c0;
                float l0 = 0.f, l1 = 0.f;
#pragma unroll
                for (int s = 0; s < 2; s++) {
                    const float* pc  = pmp  + 16 * s;
                    const float* pce = pmep + 16 * s;
                    float pm00 = pc[q2],      pm01 = pc[q2 + 1];
                    float pm10 = pc[q2 + 8],  pm11 = pc[q2 + 9];
                    float pe00 = pce[q2],     pe01 = pce[q2 + 1];
                    float pe10 = pce[q2 + 8], pe11 = pce[q2 + 9];
                    const int j0 = 2 * s, j1 = 2 * s + 1;
                    float e00 = ex2f(sacc[j0][0] * cr0 * pe00);
                    float e01 = ex2f(sacc[j0][1] * cr0 * pe01);
                    float e02 = ex2f(sacc[j0][2] * cr1 * pe00);
                    float e03 = ex2f(sacc[j0][3] * cr1 * pe01);
                    float e10 = ex2f(sacc[j1][0] * cr0 * pe10);
                    float e11 = ex2f(sacc[j1][1] * cr0 * pe11);
                    float e12 = ex2f(sacc[j1][2] * cr1 * pe10);
                    float e13 = ex2f(sacc[j1][3] * cr1 * pe11);
                    l0 += e00 + e01 + e10 + e11;
                    l1 += e02 + e03 + e12 + e13;
                    uint32_t ra0 = packbf(e00 * pm00, e01 * pm01);
                    uint32_t ra1 = packbf(e02 * pm00, e03 * pm01);
                    uint32_t ra2 = packbf(e10 * pm10, e11 * pm11);
                    uint32_t ra3 = packbf(e12 * pm10, e13 * pm11);
#pragma unroll
                    for (int dt = 0; dt < 4; dt++)
                        mma16816(oacc[i][dt], ra0, ra1, ra2, ra3,
                                 vr[s][dt >> 1][(dt & 1) * 2],
                                 vr[s][dt >> 1][(dt & 1) * 2 + 1]);
                }
                lacc[i][0] += l0;
                lacc[i][1] += l1;
            }
        }
        buf ^= 1;
    }

    float inv0[KCL], inv1[KCL];
#pragma unroll
    for (int i = 0; i < KCL; i++) {
        float l0 = lacc[i][0], l1 = lacc[i][1];
        l0 += __shfl_xor_sync(0xffffffffu, l0, 1);
        l0 += __shfl_xor_sync(0xffffffffu, l0, 2);
        l1 += __shfl_xor_sync(0xffffffffu, l1, 1);
        l1 += __shfl_xor_sync(0xffffffffu, l1, 2);
        inv0[i] = __fdividef(1.f, 3.f * l0);
        inv1[i] = __fdividef(1.f, 3.f * l1);
    }

    __nv_bfloat16* ob0 = g_attt + ((size_t)b * NTOK + n_g)     * C2D + h * DHEAD;
    __nv_bfloat16* ob1 = g_attt + ((size_t)b * NTOK + n_g + 8) * C2D + h * DHEAD;
#pragma unroll
    for (int dt = 0; dt < 4; dt++) {
        int d0 = dt * 8 + q2;
        float o00 = 0.f, o01 = 0.f, o10 = 0.f, o11 = 0.f;
#pragma unroll
        for (int i = 0; i < KCL; i++) {
            o00 += oacc[i][dt][0] * inv0[i];
            o01 += oacc[i][dt][1] * inv0[i];
            o10 += oacc[i][dt][2] * inv1[i];
            o11 += oacc[i][dt][3] * inv1[i];
        }
        *(uint32_t*)(ob0 + d0) = packbf(o00, o01);
        *(uint32_t*)(ob1 + d0) = packbf(o10, o11);
    }
}

// ---------------- converts -------------------------------------------------
__global__ __launch_bounds__(256) void conv_w(
    const float* __restrict__ Wq, const float* __restrict__ Wp)
{
    int idx = blockIdx.x * 256 + threadIdx.x;
    if (idx < 3 * C2D * C2D) g_wqh[idx] = __float2bfloat16(Wq[idx]);
    else {
        int j = idx - 3 * C2D * C2D;
        if (j < C2D * C2D) g_wph[j] = __float2bfloat16(Wp[j]);
    }
}

// ---------------- cluster probs --------------------------------------------
__global__ __launch_bounds__(256) void prob_kernel(
    const float* __restrict__ Wc, const float* __restrict__ bc)
{
    __shared__ float W[KCL * C2D];
    __shared__ float bias[KCL];
    const int t = threadIdx.x;
    for (int i = t; i < KCL * C2D; i += 256) W[i] = Wc[i];
    if (t < KCL) bias[t] = bc[t];
    __syncthreads();

    const int gidx = blockIdx.x * 256 + t;
    const int tok = gidx >> 2;
    const int p   = t & 3;
    const int b = tok >> 10, n = tok & 1023;

    const __nv_bfloat16* xp = g_xft + ((size_t)(b * NTOK + n)) * C2D + p * 64;
    const float* W0 = W + p * 64;
    float l0 = 0.f, l1 = 0.f, l2 = 0.f;
#pragma unroll
    for (int j = 0; j < 8; j++) {
        uint4 v = *(const uint4*)(xp + j * 8);
        const float* w = W0 + j * 8;
        float x0 = bflo(v.x), x1 = bfhi(v.x);
        float x2 = bflo(v.y), x3 = bfhi(v.y);
        float x4 = bflo(v.z), x5 = bfhi(v.z);
        float x6 = bflo(v.w), x7 = bfhi(v.w);
        l0 = fmaf(w[0], x0, l0); l0 = fmaf(w[1], x1, l0);
        l0 = fmaf(w[2], x2, l0); l0 = fmaf(w[3], x3, l0);
        l0 = fmaf(w[4], x4, l0); l0 = fmaf(w[5], x5, l0);
        l0 = fmaf(w[6], x6, l0); l0 = fmaf(w[7], x7, l0);
        l1 = fmaf(w[C2D + 0], x0, l1); l1 = fmaf(w[C2D + 1], x1, l1);
        l1 = fmaf(w[C2D + 2], x2, l1); l1 = fmaf(w[C2D + 3], x3, l1);
        l1 = fmaf(w[C2D + 4], x4, l1); l1 = fmaf(w[C2D + 5], x5, l1);
        l1 = fmaf(w[C2D + 6], x6, l1); l1 = fmaf(w[C2D + 7], x7, l1);
        l2 = fmaf(w[2 * C2D + 0], x0, l2); l2 = fmaf(w[2 * C2D + 1], x1, l2);
        l2 = fmaf(w[2 * C2D + 2], x2, l2); l2 = fmaf(w[2 * C2D + 3], x3, l2);
        l2 = fmaf(w[2 * C2D + 4], x4, l2); l2 = fmaf(w[2 * C2D + 5], x5, l2);
        l2 = fmaf(w[2 * C2D + 6], x6, l2); l2 = fmaf(w[2 * C2D + 7], x7, l2);
    }
    l0 += __shfl_xor_sync(0xffffffffu, l0, 1);
    l0 += __shfl_xor_sync(0xffffffffu, l0, 2);
    l1 += __shfl_xor_sync(0xffffffffu, l1, 1);
    l1 += __shfl_xor_sync(0xffffffffu, l1, 2);
    l2 += __shfl_xor_sync(0xffffffffu, l2, 1);
    l2 += __shfl_xor_sync(0xffffffffu, l2, 2);

    if (p == 0) {
        l0 += bias[0]; l1 += bias[1]; l2 += bias[2];
        float mx = fmaxf(l0, fmaxf(l1, l2));
        float e0 = __expf(l0 - mx), e1 = __expf(l1 - mx), e2 = __expf(l2 - mx);
        float inv = 1.f / (e0 + e1 + e2);
        float p0 = e0 * inv, p1 = e1 * inv, p2 = e2 * inv;
        float* pb  = g_prob  + (size_t)b * KCL * NTOK + n;
        float* peb = g_probe + (size_t)b * KCL * NTOK + n;
        pb[0]        = p0;  peb[0]        = p0 * EXPSC;
        pb[NTOK]     = p1;  peb[NTOK]     = p1 * EXPSC;
        pb[2 * NTOK] = p2;  peb[2 * NTOK] = p2 * EXPSC;
    }
}

// ---------------- launch ---------------------------------------------------
extern "C" void kernel_launch(void* const* d_in, const int* in_sizes, int n_in,
                              void* d_out, int out_size)
{
    const float* x      = (const float*)d_in[0];
    const float* W_in   = (const float*)d_in[1];
    const float* Wc     = (const float*)d_in[2];
    const float* bc     = (const float*)d_in[3];
    const float* W_qkv  = (const float*)d_in[4];
    const float* W_proj = (const float*)d_in[5];
    float* out = (float*)d_out;

    float* xf;
    __nv_bfloat16 *wqh, *wph, *xft, *attt;
    cudaGetSymbolAddress((void**)&xf,   g_xf);
    cudaGetSymbolAddress((void**)&wqh,  g_wqh);
    cudaGetSymbolAddress((void**)&wph,  g_wph);
    cudaGetSymbolAddress((void**)&xft,  g_xft);
    cudaGetSymbolAddress((void**)&attt, g_attt);

    // 1) xf = W_in @ x (tf32 tensor) + fused bf16 transpose to xft
    gemm_in<<<dim3(16, 4, BDIM), 128>>>(W_in, x);
    // 2) weight conversions + cluster probs (from xft)
    conv_w<<<1024, 256>>>(W_qkv, W_proj);
    prob_kernel<<<(BDIM * NTOK * 4) / 256, 256>>>(Wc, bc);
    // 3) qkv GEMM (bf16 + ldmatrix, K-chunked), fused q/k/v epilogue
    gemm_h<<<dim3(16, 12, BDIM), 128>>>(wqh, xft, nullptr, nullptr, 1);
    // 4) clustered attention (cp.async pipelined)
    attn_kernel<<<dim3(NTOK / ROWT, NHEAD, BDIM), 128>>>();
    // 5) out = W_proj @ att + xf
    gemm_h<<<dim3(16, 4, BDIM), 128>>>(wph, attt, out, xf, 0);
}

// round 14
// speedup vs baseline: 7.5810x; 1.0005x over previous
#include <cuda_runtime.h>
#include <cuda_bf16.h>
#include <math.h>
#include <stdint.h>

#define BDIM  8
#define C2D   256
#define NTOK  1024
#define NHEAD 8
#define DHEAD 32
#define KCL   3
#define QKSCALE 0.17677669529663687f
#define EXPSC  (0.17677669529663687f * 1.4426950408889634f)

// ---------------- scratch ----------------
__device__ float g_xf  [BDIM * C2D * NTOK];
__device__ float g_prob[BDIM * KCL * NTOK];
__device__ float g_probe[BDIM * KCL * NTOK];
__device__ __nv_bfloat16 g_xft [BDIM * NTOK * C2D];
__device__ __nv_bfloat16 g_qh  [BDIM * NHEAD * NTOK * DHEAD];
__device__ __nv_bfloat16 g_kh  [BDIM * NHEAD * NTOK * DHEAD];
__device__ __nv_bfloat16 g_vh  [BDIM * NHEAD * DHEAD * NTOK];
__device__ __nv_bfloat16 g_attt[BDIM * NTOK * C2D];

// ---------------- helpers ----------------
__device__ __forceinline__ uint32_t smem_u32(const void* p) {
    uint32_t a;
    asm("{ .reg .u64 t; cvta.to.shared.u64 t, %1; cvt.u32.u64 %0, t; }" : "=r"(a) : "l"(p));
    return a;
}
__device__ __forceinline__ void mma16816(float* d,
    uint32_t a0, uint32_t a1, uint32_t a2, uint32_t a3,
    uint32_t b0, uint32_t b1)
{
    asm volatile(
        "mma.sync.aligned.m16n8k16.row.col.f32.bf16.bf16.f32 "
        "{%0,%1,%2,%3}, {%4,%5,%6,%7}, {%8,%9}, {%0,%1,%2,%3};"
        : "+f"(d[0]), "+f"(d[1]), "+f"(d[2]), "+f"(d[3])
        : "r"(a0), "r"(a1), "r"(a2), "r"(a3), "r"(b0), "r"(b1));
}
__device__ __forceinline__ void mma1688tf(float* d,
    uint32_t a0, uint32_t a1, uint32_t a2, uint32_t a3,
    uint32_t b0, uint32_t b1)
{
    asm volatile(
        "mma.sync.aligned.m16n8k8.row.col.f32.tf32.tf32.f32 "
        "{%0,%1,%2,%3}, {%4,%5,%6,%7}, {%8,%9}, {%0,%1,%2,%3};"
        : "+f"(d[0]), "+f"(d[1]), "+f"(d[2]), "+f"(d[3])
        : "r"(a0), "r"(a1), "r"(a2), "r"(a3), "r"(b0), "r"(b1));
}
__device__ __forceinline__ void ldsm4(uint32_t* r, uint32_t addr) {
    asm volatile("ldmatrix.sync.aligned.m8n8.x4.shared.b16 {%0,%1,%2,%3}, [%4];"
        : "=r"(r[0]), "=r"(r[1]), "=r"(r[2]), "=r"(r[3]) : "r"(addr));
}
__device__ __forceinline__ uint32_t packbf(float lo, float hi) {
    __nv_bfloat162 p = __floats2bfloat162_rn(lo, hi);
    return *(uint32_t*)&p;
}
__device__ __forceinline__ float ex2f(float x) {
    float r; asm("ex2.approx.ftz.f32 %0, %1;" : "=f"(r) : "f"(x)); return r;
}
__device__ __forceinline__ float bflo(uint32_t u) { return __uint_as_float(u << 16); }
__device__ __forceinline__ float bfhi(uint32_t u) { return __uint_as_float(u & 0xffff0000u); }
__device__ __forceinline__ uint32_t f2tf32(float x) {
    uint32_t r; asm("cvt.rna.tf32.f32 %0, %1;" : "=r"(r) : "f"(x)); return r;
}
__device__ __forceinline__ void cpa16(uint32_t s, const void* g) {
    asm volatile("{ .reg .u64 gg; cvta.to.global.u64 gg, %1; "
                 "cp.async.cg.shared.global [%0], [gg], 16; }" :: "r"(s), "l"(g));
}
__device__ __forceinline__ void cpa4(uint32_t s, const void* g) {
    asm volatile("{ .reg .u64 gg; cvta.to.global.u64 gg, %1; "
                 "cp.async.ca.shared.global [%0], [gg], 4; }" :: "r"(s), "l"(g));
}
#define CP_COMMIT() asm volatile("cp.async.commit_group;" ::: "memory")
#define CP_WAIT1()  asm volatile("cp.async.wait_group 1;" ::: "memory")
#define CP_WAIT0()  asm volatile("cp.async.wait_group 0;" ::: "memory")

// ---------------- tf32 GEMM for proj_in: xf = W_in @ x, + xft bf16 ---------
__global__ __launch_bounds__(128) void gemm_in(
    const float* __restrict__ W, const float* __restrict__ X)
{
    __shared__ uint32_t As[64 * 68];
    __shared__ uint32_t Bs[64 * 68];

    const int t = threadIdx.x;
    const int lane = t & 31, wid = t >> 5;
    const int gid = lane >> 2, kl = lane & 3, q2 = kl * 2;
    const int mblk = blockIdx.y * 64, nblk = blockIdx.x * 64, b = blockIdx.z;
    const int wm = wid * 16;

    float acc[8][4];
#pragma unroll
    for (int nt = 0; nt < 8; nt++)
#pragma unroll
        for (int j = 0; j < 4; j++) acc[nt][j] = 0.f;

    for (int ks = 0; ks < 128; ks += 64) {
        __syncthreads();
#pragma unroll
        for (int i = 0; i < 8; i++) {
            int idx = t + i * 128;
            int row = idx >> 4, c4 = (idx & 15) * 4;
            float4 av = *(const float4*)(W + (size_t)(mblk + row) * 128 + ks + c4);
            As[row * 68 + c4 + 0] = f2tf32(av.x);
            As[row * 68 + c4 + 1] = f2tf32(av.y);
            As[row * 68 + c4 + 2] = f2tf32(av.z);
            As[row * 68 + c4 + 3] = f2tf32(av.w);
            float4 bv = *(const float4*)(X + (size_t)b * 131072 +
                                         (size_t)(ks + row) * NTOK + nblk + c4);
            Bs[(c4 + 0) * 68 + row] = f2tf32(bv.x);
            Bs[(c4 + 1) * 68 + row] = f2tf32(bv.y);
            Bs[(c4 + 2) * 68 + row] = f2tf32(bv.z);
            Bs[(c4 + 3) * 68 + row] = f2tf32(bv.w);
        }
        __syncthreads();
#pragma unroll
        for (int kk = 0; kk < 64; kk += 8) {
            uint32_t a0 = As[(wm + gid) * 68 + kk + kl];
            uint32_t a1 = As[(wm + gid + 8) * 68 + kk + kl];
            uint32_t a2 = As[(wm + gid) * 68 + kk + kl + 4];
            uint32_t a3 = As[(wm + gid + 8) * 68 + kk + kl + 4];
#pragma unroll
            for (int nt = 0; nt < 8; nt++) {
                uint32_t b0 = Bs[(nt * 8 + gid) * 68 + kk + kl];
                uint32_t b1 = Bs[(nt * 8 + gid) * 68 + kk + kl + 4];
                mma1688tf(acc[nt], a0, a1, a2, a3, b0, b1);
            }
        }
    }

    float* xfb = g_xf + (size_t)b * C2D * NTOK;
    __nv_bfloat16* xtb = g_xft + (size_t)b * NTOK * C2D;
    const int r0 = mblk + wm + gid;
#pragma unroll
    for (int nt = 0; nt < 8; nt++) {
        int col = nblk + nt * 8 + q2;
        *(float2*)(xfb + (size_t)r0 * NTOK + col) =
            make_float2(acc[nt][0], acc[nt][1]);
        *(float2*)(xfb + (size_t)(r0 + 8) * NTOK + col) =
            make_float2(acc[nt][2], acc[nt][3]);
        xtb[(size_t)col * C2D + r0]           = __float2bfloat16(acc[nt][0]);
        xtb[(size_t)(col + 1) * C2D + r0]     = __float2bfloat16(acc[nt][1]);
        xtb[(size_t)col * C2D + r0 + 8]       = __float2bfloat16(acc[nt][2]);
        xtb[(size_t)(col + 1) * C2D + r0 + 8] = __float2bfloat16(acc[nt][3]);
    }
}

// ---------------- bf16 GEMM (wide warp tile 32x64, fp32 A converted) -------
#define GK   256
#define GCH  128
#define GLD2 136
#define GH_SMEM ((128 + 64) * GLD2 * 2)
__global__ __launch_bounds__(128) void gemm_h(
    const float* __restrict__ Af, const __nv_bfloat16* __restrict__ Xt,
    float* __restrict__ C, const float* __restrict__ add_src, int mode)
{
    extern __shared__ __nv_bfloat16 gh[];
    __nv_bfloat16* As = gh;                 // [128][GLD2]
    __nv_bfloat16* Bs = gh + 128 * GLD2;    // [64][GLD2]

    const int t = threadIdx.x;
    const int lane = t & 31, wid = t >> 5;
    const int gid = lane >> 2, q2 = (lane & 3) * 2;
    const int lrow = lane & 7, lmi = lane >> 3;
    const int mblk = blockIdx.y * 128, nblk = blockIdx.x * 64, b = blockIdx.z;
    const int wm = wid * 32;

    const __nv_bfloat16* Xb = Xt + ((size_t)b * NTOK + nblk) * GK;
    const uint32_t as_b = smem_u32(As);
    const uint32_t bs_b = smem_u32(Bs);
    const uint32_t a_addr0 = as_b + 2 * ((wm + ((lmi & 1) << 3) + lrow) * GLD2 + ((lmi >> 1) << 3));
    const uint32_t a_addr1 = a_addr0 + 2 * (16 * GLD2);
    const uint32_t b_row   = (uint32_t)(((lmi >> 1) << 3) + lrow) * GLD2 + ((lmi & 1) << 3);

    float acc[2][8][4];
#pragma unroll
    for (int mi = 0; mi < 2; mi++)
#pragma unroll
        for (int nt = 0; nt < 8; nt++)
#pragma unroll
            for (int j = 0; j < 4; j++) acc[mi][nt][j] = 0.f;

#pragma unroll
    for (int kc = 0; kc < 2; kc++) {
        __syncthreads();
        const float* Ab = Af + (size_t)mblk * GK + kc * GCH;
        const __nv_bfloat16* Bb = Xb + kc * GCH;
        // A: 128x128 fp32 -> bf16 smem
#pragma unroll
        for (int i = 0; i < 16; i++) {
            int idx = t + i * 128;
            int row = idx >> 4, q = (idx & 15) * 8;
            float4 v0 = *(const float4*)(Ab + (size_t)row * GK + q);
            float4 v1 = *(const float4*)(Ab + (size_t)row * GK + q + 4);
            uint4 w;
            w.x = packbf(v0.x, v0.y); w.y = packbf(v0.z, v0.w);
            w.z = packbf(v1.x, v1.y); w.w = packbf(v1.z, v1.w);
            *(uint4*)(As + row * GLD2 + q) = w;
        }
        // B: 64x128 bf16
#pragma unroll
        for (int i = 0; i < 8; i++) {
            int idx = t + i * 128;
            int row = idx >> 4, q = (idx & 15) * 8;
            *(uint4*)(Bs + row * GLD2 + q) = *(const uint4*)(Bb + (size_t)row * GK + q);
        }
        __syncthreads();
#pragma unroll
        for (int kt = 0; kt < GCH / 16; kt++) {
            const int ka = kt * 16;
            uint32_t ar[2][4];
            ldsm4(ar[0], a_addr0 + 2 * ka);
            ldsm4(ar[1], a_addr1 + 2 * ka);
#pragma unroll
            for (int np = 0; np < 4; np++) {
                uint32_t br[4];
                ldsm4(br, bs_b + 2 * (b_row + (np * 16) * GLD2 + ka));
#pragma unroll
                for (int mi = 0; mi < 2; mi++) {
                    mma16816(acc[mi][2 * np],     ar[mi][0], ar[mi][1], ar[mi][2], ar[mi][3], br[0], br[1]);
                    mma16816(acc[mi][2 * np + 1], ar[mi][0], ar[mi][1], ar[mi][2], ar[mi][3], br[2], br[3]);
                }
            }
        }
    }

#pragma unroll
    for (int mi = 0; mi < 2; mi++) {
        const int r0 = mblk + wm + mi * 16 + gid;
        if (mode == 1) {
            const int sector = r0 >> 8;
            const int hh = (r0 >> 5) & 7, dd = r0 & 31;
            if (sector < 2) {
                __nv_bfloat16* base = (sector == 0 ? g_qh : g_kh) +
                    (size_t)(b * NHEAD + hh) * NTOK * DHEAD;
#pragma unroll
                for (int nt = 0; nt < 8; nt++) {
                    int n = nblk + nt * 8 + q2;
                    base[(size_t)n * DHEAD + dd]           = __float2bfloat16(acc[mi][nt][0]);
                    base[(size_t)(n + 1) * DHEAD + dd]     = __float2bfloat16(acc[mi][nt][1]);
                    base[(size_t)n * DHEAD + dd + 8]       = __float2bfloat16(acc[mi][nt][2]);
                    base[(size_t)(n + 1) * DHEAD + dd + 8] = __float2bfloat16(acc[mi][nt][3]);
                }
            } else {
                __nv_bfloat16* vb = g_vh + (size_t)(b * NHEAD + hh) * DHEAD * NTOK;
#pragma unroll
                for (int nt = 0; nt < 8; nt++) {
                    int n = nblk + nt * 8 + q2;
                    *(uint32_t*)(vb + (size_t)dd * NTOK + n)       = packbf(acc[mi][nt][0], acc[mi][nt][1]);
                    *(uint32_t*)(vb + (size_t)(dd + 8) * NTOK + n) = packbf(acc[mi][nt][2], acc[mi][nt][3]);
                }
            }
        } else {
            float* Cb = C + (size_t)b * C2D * NTOK;
            const float* ab = add_src + (size_t)b * C2D * NTOK;
#pragma unroll
            for (int nt = 0; nt < 8; nt++) {
                int col = nblk + nt * 8 + q2;
                float2 a0 = *(const float2*)(ab + (size_t)r0 * NTOK + col);
                float2 a1 = *(const float2*)(ab + (size_t)(r0 + 8) * NTOK + col);
                *(float2*)(Cb + (size_t)r0 * NTOK + col) =
                    make_float2(acc[mi][nt][0] + a0.x, acc[mi][nt][1] + a0.y);
                *(float2*)(Cb + (size_t)(r0 + 8) * NTOK + col) =
                    make_float2(acc[mi][nt][2] + a1.x, acc[mi][nt][3] + a1.y);
            }
        }
    }
}

// ---------------- attention (unchanged from R13) ---------------------------
#define ROWT 64
#define KS_LD 40
#define VT_LD 136
#define KS_BYTES (128 * KS_LD * 2)
#define VT_BYTES (DHEAD * VT_LD * 2)

__global__ void __launch_bounds__(128, 4) attn_kernel()
{
    __shared__ __align__(16) __nv_bfloat16 Ks[2][128 * KS_LD];
    __shared__ __align__(16) __nv_bfloat16 Vt[2][DHEAD * VT_LD];
    __shared__ float pm_s [2][KCL * 128];
    __shared__ float pme_s[2][KCL * 128];

    const int t    = threadIdx.x;
    const int wid  = t >> 5;
    const int lane = t & 31;
    const int gid  = lane >> 2;
    const int q2   = (lane & 3) * 2;
    const int lrow = lane & 7, lmi = lane >> 3;

    const int n0 = blockIdx.x * ROWT;
    const int h  = blockIdx.y;
    const int b  = blockIdx.z;

    const __nv_bfloat16* qh = g_qh + (size_t)(b * NHEAD + h) * NTOK * DHEAD;
    const __nv_bfloat16* kh = g_kh + (size_t)(b * NHEAD + h) * NTOK * DHEAD;
    const __nv_bfloat16* vh = g_vh + (size_t)(b * NHEAD + h) * DHEAD * NTOK;
    const float* pbase  = g_prob  + (size_t)b * KCL * NTOK;
    const float* pebase = g_probe + (size_t)b * KCL * NTOK;

    const int n_g = n0 + wid * 16 + gid;

    const uint32_t ks_u  = smem_u32(Ks);
    const uint32_t vt_u  = smem_u32(Vt);
    const uint32_t pm_u  = smem_u32(pm_s);
    const uint32_t pme_u = smem_u32(pme_s);

    const int st_krow = t >> 2, st_kq = (t & 3) * 8;
    const int st_vd   = t >> 4, st_vq = (t & 15) * 8;
    auto stage = [&](int mt, int bufi) {
        uint32_t kb = ks_u + bufi * KS_BYTES;
        uint32_t vb = vt_u + bufi * VT_BYTES;
#pragma unroll
        for (int i = 0; i < 4; i++) {
            int row = st_krow + i * 32;
            cpa16(kb + (uint32_t)(row * KS_LD + st_kq) * 2,
                  kh + (size_t)(mt + row) * DHEAD + st_kq);
        }
#pragma unroll
        for (int i = 0; i < 4; i++) {
            int d = st_vd + i * 8;
            cpa16(vb + (uint32_t)(d * VT_LD + st_vq) * 2,
                  vh + (size_t)d * NTOK + mt + st_vq);
        }
#pragma unroll
        for (int i = 0; i < 3; i++) {
            int idx = t + i * 128;
            int cl = idx >> 7, m = idx & 127;
            cpa4(pm_u  + (uint32_t)(bufi * KCL * 128 + cl * 128 + m) * 4,
                 pbase  + (size_t)cl * NTOK + mt + m);
            cpa4(pme_u + (uint32_t)(bufi * KCL * 128 + cl * 128 + m) * 4,
                 pebase + (size_t)cl * NTOK + mt + m);
        }
    };

    uint32_t qa[2][4];
#pragma unroll
    for (int kt = 0; kt < 2; kt++) {
        int d0 = kt * 16 + q2;
        qa[kt][0] = *(const uint32_t*)(qh + (size_t)n_g * DHEAD + d0);
        qa[kt][1] = *(const uint32_t*)(qh + (size_t)(n_g + 8) * DHEAD + d0);
        qa[kt][2] = *(const uint32_t*)(qh + (size_t)n_g * DHEAD + d0 + 8);
        qa[kt][3] = *(const uint32_t*)(qh + (size_t)(n_g + 8) * DHEAD + d0 + 8);
    }

    float pn0[KCL], pn1[KCL];
#pragma unroll
    for (int i = 0; i < KCL; i++) {
        pn0[i] = pbase[i * NTOK + n_g];
        pn1[i] = pbase[i * NTOK + n_g + 8];
    }

    float oacc[KCL][4][4];
    float lacc[KCL][2];
#pragma unroll
    for (int i = 0; i < KCL; i++) {
        lacc[i][0] = lacc[i][1] = 0.f;
#pragma unroll
        for (int dt = 0; dt < 4; dt++)
#pragma unroll
            for (int j = 0; j < 4; j++) oacc[i][dt][j] = 0.f;
    }

    const uint32_t k_off = (uint32_t)lrow * KS_LD + lmi * 8;
    const uint32_t v_off = (uint32_t)(((lmi >> 1) << 3) + lrow) * VT_LD + ((lmi & 1) << 3);

    stage(0, 0);
    CP_COMMIT();

    int buf = 0;
    for (int it = 0; it < 8; it++) {
        if (it) __syncthreads();
        if (it < 7) { stage((it + 1) * 128, buf ^ 1); CP_COMMIT(); CP_WAIT1(); }
        else CP_WAIT0();
        __syncthreads();

        const uint32_t ks_b = ks_u + buf * KS_BYTES;
        const uint32_t vt_b = vt_u + buf * VT_BYTES;
        const float* pmb  = pm_s [buf];
        const float* pmeb = pme_s[buf];

#pragma unroll
        for (int chunk = 0; chunk < 4; chunk++) {
            const int c0 = chunk * 32;
            float sacc[4][4];
#pragma unroll
            for (int nt = 0; nt < 4; nt++) {
                sacc[nt][0] = sacc[nt][1] = sacc[nt][2] = sacc[nt][3] = 0.f;
                uint32_t br[4];
                ldsm4(br, ks_b + 2 * ((uint32_t)(c0 + nt * 8) * KS_LD + k_off));
                mma16816(sacc[nt], qa[0][0], qa[0][1], qa[0][2], qa[0][3], br[0], br[1]);
                mma16816(sacc[nt], qa[1][0], qa[1][1], qa[1][2], qa[1][3], br[2], br[3]);
            }
            uint32_t vr[2][2][4];
#pragma unroll
            for (int s = 0; s < 2; s++)
#pragma unroll
                for (int dp = 0; dp < 2; dp++)
                    ldsm4(vr[s][dp], vt_b + 2 * ((uint32_t)(dp * 16) * VT_LD + v_off
                                               + (uint32_t)(c0 + 16 * s)));

#pragma unroll
            for (int i = 0; i < KCL; i++) {
                const float cr0 = pn0[i], cr1 = pn1[i];
                const float* pmp  = pmb  + i * 128 + c0;
                const float* pmep = pmeb + i * 128 + c0;
                float l0 = 0.f, l1 = 0.f;
#pragma unroll
                for (int s = 0; s < 2; s++) {
                    const float* pc  = pmp  + 16 * s;
                    const float* pce = pmep + 16 * s;
                    float pm00 = pc[q2],      pm01 = pc[q2 + 1];
                    float pm10 = pc[q2 + 8],  pm11 = pc[q2 + 9];
                    float pe00 = pce[q2],     pe01 = pce[q2 + 1];
                    float pe10 = pce[q2 + 8], pe11 = pce[q2 + 9];
                    const int j0 = 2 * s, j1 = 2 * s + 1;
                    float e00 = ex2f(sacc[j0][0] * cr0 * pe00);
                    float e01 = ex2f(sacc[j0][1] * cr0 * pe01);
                    float e02 = ex2f(sacc[j0][2] * cr1 * pe00);
                    float e03 = ex2f(sacc[j0][3] * cr1 * pe01);
                    float e10 = ex2f(sacc[j1][0] * cr0 * pe10);
                    float e11 = ex2f(sacc[j1][1] * cr0 * pe11);
                    float e12 = ex2f(sacc[j1][2] * cr1 * pe10);
                    float e13 = ex2f(sacc[j1][3] * cr1 * pe11);
                    l0 += e00 + e01 + e10 + e11;
                    l1 += e02 + e03 + e12 + e13;
                    uint32_t ra0 = packbf(e00 * pm00, e01 * pm01);
                    uint32_t ra1 = packbf(e02 * pm00, e03 * pm01);
                    uint32_t ra2 = packbf(e10 * pm10, e11 * pm11);
                    uint32_t ra3 = packbf(e12 * pm10, e13 * pm11);
#pragma unroll
                    for (int dt = 0; dt < 4; dt++)
                        mma16816(oacc[i][dt], ra0, ra1, ra2, ra3,
                                 vr[s][dt >> 1][(dt & 1) * 2],
                                 vr[s][dt >> 1][(dt & 1) * 2 + 1]);
                }
                lacc[i][0] += l0;
                lacc[i][1] += l1;
            }
        }
        buf ^= 1;
    }

    float inv0[KCL], inv1[KCL];
#pragma unroll
    for (int i = 0; i < KCL; i++) {
        float l0 = lacc[i][0], l1 = lacc[i][1];
        l0 += __shfl_xor_sync(0xffffffffu, l0, 1);
        l0 += __shfl_xor_sync(0xffffffffu, l0, 2);
        l1 += __shfl_xor_sync(0xffffffffu, l1, 1);
        l1 += __shfl_xor_sync(0xffffffffu, l1, 2);
        inv0[i] = __fdividef(1.f, 3.f * l0);
        inv1[i] = __fdividef(1.f, 3.f * l1);
    }

    __nv_bfloat16* ob0 = g_attt + ((size_t)b * NTOK + n_g)     * C2D + h * DHEAD;
    __nv_bfloat16* ob1 = g_attt + ((size_t)b * NTOK + n_g + 8) * C2D + h * DHEAD;
#pragma unroll
    for (int dt = 0; dt < 4; dt++) {
        int d0 = dt * 8 + q2;
        float o00 = 0.f, o01 = 0.f, o10 = 0.f, o11 = 0.f;
#pragma unroll
        for (int i = 0; i < KCL; i++) {
            o00 += oacc[i][dt][0] * inv0[i];
            o01 += oacc[i][dt][1] * inv0[i];
            o10 += oacc[i][dt][2] * inv1[i];
            o11 += oacc[i][dt][3] * inv1[i];
        }
        *(uint32_t*)(ob0 + d0) = packbf(o00, o01);
        *(uint32_t*)(ob1 + d0) = packbf(o10, o11);
    }
}

// ---------------- cluster probs --------------------------------------------
__global__ __launch_bounds__(256) void prob_kernel(
    const float* __restrict__ Wc, const float* __restrict__ bc)
{
    __shared__ float W[KCL * C2D];
    __shared__ float bias[KCL];
    const int t = threadIdx.x;
    for (int i = t; i < KCL * C2D; i += 256) W[i] = Wc[i];
    if (t < KCL) bias[t] = bc[t];
    __syncthreads();

    const int gidx = blockIdx.x * 256 + t;
    const int tok = gidx >> 2;
    const int p   = t & 3;
    const int b = tok >> 10, n = tok & 1023;

    const __nv_bfloat16* xp = g_xft + ((size_t)(b * NTOK + n)) * C2D + p * 64;
    const float* W0 = W + p * 64;
    float l0 = 0.f, l1 = 0.f, l2 = 0.f;
#pragma unroll
    for (int j = 0; j < 8; j++) {
        uint4 v = *(const uint4*)(xp + j * 8);
        const float* w = W0 + j * 8;
        float x0 = bflo(v.x), x1 = bfhi(v.x);
        float x2 = bflo(v.y), x3 = bfhi(v.y);
        float x4 = bflo(v.z), x5 = bfhi(v.z);
        float x6 = bflo(v.w), x7 = bfhi(v.w);
        l0 = fmaf(w[0], x0, l0); l0 = fmaf(w[1], x1, l0);
        l0 = fmaf(w[2], x2, l0); l0 = fmaf(w[3], x3, l0);
        l0 = fmaf(w[4], x4, l0); l0 = fmaf(w[5], x5, l0);
        l0 = fmaf(w[6], x6, l0); l0 = fmaf(w[7], x7, l0);
        l1 = fmaf(w[C2D + 0], x0, l1); l1 = fmaf(w[C2D + 1], x1, l1);
        l1 = fmaf(w[C2D + 2], x2, l1); l1 = fmaf(w[C2D + 3], x3, l1);
        l1 = fmaf(w[C2D + 4], x4, l1); l1 = fmaf(w[C2D + 5], x5, l1);
        l1 = fmaf(w[C2D + 6], x6, l1); l1 = fmaf(w[C2D + 7], x7, l1);
        l2 = fmaf(w[2 * C2D + 0], x0, l2); l2 = fmaf(w[2 * C2D + 1], x1, l2);
        l2 = fmaf(w[2 * C2D + 2], x2, l2); l2 = fmaf(w[2 * C2D + 3], x3, l2);
        l2 = fmaf(w[2 * C2D + 4], x4, l2); l2 = fmaf(w[2 * C2D + 5], x5, l2);
        l2 = fmaf(w[2 * C2D + 6], x6, l2); l2 = fmaf(w[2 * C2D + 7], x7, l2);
    }
    l0 += __shfl_xor_sync(0xffffffffu, l0, 1);
    l0 += __shfl_xor_sync(0xffffffffu, l0, 2);
    l1 += __shfl_xor_sync(0xffffffffu, l1, 1);
    l1 += __shfl_xor_sync(0xffffffffu, l1, 2);
    l2 += __shfl_xor_sync(0xffffffffu, l2, 1);
    l2 += __shfl_xor_sync(0xffffffffu, l2, 2);

    if (p == 0) {
        l0 += bias[0]; l1 += bias[1]; l2 += bias[2];
        float mx = fmaxf(l0, fmaxf(l1, l2));
        float e0 = __expf(l0 - mx), e1 = __expf(l1 - mx), e2 = __expf(l2 - mx);
        float inv = 1.f / (e0 + e1 + e2);
        float p0 = e0 * inv, p1 = e1 * inv, p2 = e2 * inv;
        float* pb  = g_prob  + (size_t)b * KCL * NTOK + n;
        float* peb = g_probe + (size_t)b * KCL * NTOK + n;
        pb[0]        = p0;  peb[0]        = p0 * EXPSC;
        pb[NTOK]     = p1;  peb[NTOK]     = p1 * EXPSC;
        pb[2 * NTOK] = p2;  peb[2 * NTOK] = p2 * EXPSC;
    }
}

// ---------------- launch ---------------------------------------------------
extern "C" void kernel_launch(void* const* d_in, const int* in_sizes, int n_in,
                              void* d_out, int out_size)
{
    const float* x      = (const float*)d_in[0];
    const float* W_in   = (const float*)d_in[1];
    const float* Wc     = (const float*)d_in[2];
    const float* bc     = (const float*)d_in[3];
    const float* W_qkv  = (const float*)d_in[4];
    const float* W_proj = (const float*)d_in[5];
    float* out = (float*)d_out;

    float* xf;
    __nv_bfloat16 *xft, *attt;
    cudaGetSymbolAddress((void**)&xf,   g_xf);
    cudaGetSymbolAddress((void**)&xft,  g_xft);
    cudaGetSymbolAddress((void**)&attt, g_attt);

    cudaFuncSetAttribute(gemm_h,
        cudaFuncAttributeMaxDynamicSharedMemorySize, GH_SMEM);

    // 1) xf = W_in @ x (tf32 tensor) + fused bf16 transpose to xft
    gemm_in<<<dim3(16, 4, BDIM), 128>>>(W_in, x);
    // 2) cluster probs (from xft)
    prob_kernel<<<(BDIM * NTOK * 4) / 256, 256>>>(Wc, bc);
    // 3) qkv GEMM (wide tile, converts W_qkv on the fly), fused q/k/v epilogue
    gemm_h<<<dim3(16, 6, BDIM), 128, GH_SMEM>>>(W_qkv, xft, nullptr, nullptr, 1);
    // 4) clustered attention (cp.async pipelined)
    attn_kernel<<<dim3(NTOK / ROWT, NHEAD, BDIM), 128>>>();
    // 5) out = W_proj @ att + xf (wide tile)
    gemm_h<<<dim3(16, 2, BDIM), 128, GH_SMEM>>>(W_proj, attt, out, xf, 0);
}